// round 1
// baseline (speedup 1.0000x reference)
#include <cuda_runtime.h>
#include <cuda_bf16.h>

// ---------------------------------------------------------------------------
// MultiHeadEncDecAttention: bs=4, seg=512, nv=8, n_head=8, d_q=32, d_in=256
// tokens = 16384 (row r = (b*512+s)*8+v), groups = 256 (g = (h*8+v)*4+b)
// Pipeline: q = x@WqT+b  ->  per-group attention  ->  fc + residual  ->  LN
// fp32 with packed fma.rn.f32x2 (Blackwell) everywhere in hot loops.
// ---------------------------------------------------------------------------

typedef unsigned long long ull;

#define NTOK   16384
#define DIN    256
#define SEG    512
#define DQ     32

// scratch (no allocations allowed)
__device__ float g_q[NTOK * DIN];
__device__ float g_att[NTOK * DIN];

__device__ __forceinline__ ull pack2(float lo, float hi) {
    ull r;
    asm("mov.b64 %0, {%1, %2};" : "=l"(r) : "f"(lo), "f"(hi));
    return r;
}
__device__ __forceinline__ void fma2(ull& d, ull a, ull b) {
    asm("fma.rn.f32x2 %0, %1, %2, %3;" : "=l"(d) : "l"(a), "l"(b), "l"(d));
}
__device__ __forceinline__ float2 unpack2(ull v) {
    float2 r;
    asm("mov.b64 {%0, %1}, %2;" : "=f"(r.x), "=f"(r.y) : "l"(v));
    return r;
}

// ---------------------------------------------------------------------------
// GEMM: C[16384,256] = A[16384,256] @ B^T  (+ bias[col], + optional resid)
// B given row-major as [256 outcols][256 k] -- matches both w_q_w and fc_w.
// MODE 0: A = Ap (x), C = g_q.   MODE 1: A = g_att, C = Cp (d_out), + resid.
// 128x128 tile, BK=32, 256 threads, 8x8 per thread via f32x2.
// ---------------------------------------------------------------------------
template <int MODE>
__global__ __launch_bounds__(256, 2) void gemm128(
    const float* __restrict__ Ap, const float* __restrict__ Bm,
    const float* __restrict__ bias, const float* __restrict__ resid,
    float* __restrict__ Cp)
{
    __shared__ float As[32][132];  // [k][row], 132 keeps 16B alignment (528B rows)
    __shared__ float Bs[32][132];  // [k][col]

    const float* A = (MODE == 0) ? Ap : g_att;
    float* C       = (MODE == 0) ? g_q : Cp;

    const int rb = blockIdx.y * 128;
    const int cb = blockIdx.x * 128;
    const int tid = threadIdx.x;
    const int tr = tid >> 4, tc = tid & 15;
    const int r0 = tr * 8, c0 = tc * 8;

    ull acc[8][4];
#pragma unroll
    for (int i = 0; i < 8; i++)
#pragma unroll
        for (int j = 0; j < 4; j++) acc[i][j] = 0ULL;

#pragma unroll 1
    for (int kt = 0; kt < 256; kt += 32) {
        // stage A/B chunks: 128 rows x 32 k each, 4 float4 per thread per matrix
#pragma unroll
        for (int u = 0; u < 4; u++) {
            int idx = tid + u * 256;
            int row = idx >> 3;
            int kk  = (idx & 7) * 4;
            float4 a = *(const float4*)&A[(rb + row) * 256 + kt + kk];
            As[kk + 0][row] = a.x; As[kk + 1][row] = a.y;
            As[kk + 2][row] = a.z; As[kk + 3][row] = a.w;
            float4 b = *(const float4*)&Bm[(cb + row) * 256 + kt + kk];
            Bs[kk + 0][row] = b.x; Bs[kk + 1][row] = b.y;
            Bs[kk + 2][row] = b.z; Bs[kk + 3][row] = b.w;
        }
        __syncthreads();

#pragma unroll 8
        for (int k = 0; k < 32; k++) {
            float4 a0 = *(const float4*)&As[k][r0];
            float4 a1 = *(const float4*)&As[k][r0 + 4];
            float4 b0 = *(const float4*)&Bs[k][c0];
            float4 b1 = *(const float4*)&Bs[k][c0 + 4];
            ull bp[4] = { pack2(b0.x, b0.y), pack2(b0.z, b0.w),
                          pack2(b1.x, b1.y), pack2(b1.z, b1.w) };
            float av[8] = { a0.x, a0.y, a0.z, a0.w, a1.x, a1.y, a1.z, a1.w };
#pragma unroll
            for (int i = 0; i < 8; i++) {
                ull a2 = pack2(av[i], av[i]);
#pragma unroll
                for (int j = 0; j < 4; j++) fma2(acc[i][j], a2, bp[j]);
            }
        }
        __syncthreads();
    }

#pragma unroll
    for (int i = 0; i < 8; i++) {
        int row = rb + r0 + i;
        int col = cb + c0;
        float o[8];
#pragma unroll
        for (int j = 0; j < 4; j++) {
            float2 t = unpack2(acc[i][j]);
            o[2 * j] = t.x; o[2 * j + 1] = t.y;
        }
#pragma unroll
        for (int j = 0; j < 8; j++) o[j] += bias[col + j];
        if (MODE == 1) {
#pragma unroll
            for (int j = 0; j < 8; j++) o[j] += resid[row * 256 + col + j];
        }
        float4 s0 = { o[0], o[1], o[2], o[3] };
        float4 s1 = { o[4], o[5], o[6], o[7] };
        *(float4*)&C[row * 256 + col]     = s0;
        *(float4*)&C[row * 256 + col + 4] = s1;
    }
}

// ---------------------------------------------------------------------------
// Attention: one CTA per group g=(h*8+v)*4+b. 512 threads, one query row each.
// z[512,32] and q[512,32] staged in smem; single-pass softmax (no max sub --
// logits are O(10), exp range is safe in fp32; identical math to reference).
// ---------------------------------------------------------------------------
__global__ __launch_bounds__(512, 1) void attn_kernel(
    const float* __restrict__ z)
{
    extern __shared__ float sm[];
    float* zs = sm;               // 512*32
    float* qs = sm + SEG * DQ;    // 512*36 (padded rows)

    const int g = blockIdx.x;
    const int h = g >> 5;
    const int v = (g >> 2) & 7;
    const int b = g & 3;
    const int tid = threadIdx.x;

    // load z group [512,32] (coalesced)
    {
        const float4* zg = (const float4*)(z + (size_t)g * SEG * DQ);
        float4* zd = (float4*)zs;
#pragma unroll
        for (int i = 0; i < 8; i++) zd[tid + i * 512] = zg[tid + i * 512];
    }
    // load q rows for this group's head slice (coalesced, staged padded)
#pragma unroll
    for (int i = 0; i < 8; i++) {
        int idx = tid + i * 512;
        int s = idx >> 3, j = idx & 7;
        int row = (b * SEG + s) * 8 + v;
        float4 qv = *(const float4*)&g_q[row * 256 + h * DQ + j * 4];
        *(float4*)&qs[s * 36 + j * 4] = qv;
    }
    __syncthreads();

    const int s = tid;
    ull qu[16];
#pragma unroll
    for (int j = 0; j < 8; j++) {
        float4 t4 = *(const float4*)&qs[s * 36 + j * 4];
        qu[2 * j]     = pack2(t4.x, t4.y);
        qu[2 * j + 1] = pack2(t4.z, t4.w);
    }

    ull outp[16];
#pragma unroll
    for (int j = 0; j < 16; j++) outp[j] = 0ULL;
    float denom = 0.f;
    // (1/sqrt(32)) * log2(e)  -> p = 2^(l*scale) = exp(dot/temp)
    const float scale = 0.17677669529663687f * 1.4426950408889634f;

    for (int t = 0; t < SEG; t++) {
        const float4* zrow = (const float4*)(zs + t * DQ);
        float4 zf[8];
#pragma unroll
        for (int j = 0; j < 8; j++) zf[j] = zrow[j];

        ull d0 = 0ULL, d1 = 0ULL;
#pragma unroll
        for (int j = 0; j < 4; j++) {
            fma2(d0, qu[4 * j + 0], pack2(zf[2 * j].x,     zf[2 * j].y));
            fma2(d1, qu[4 * j + 1], pack2(zf[2 * j].z,     zf[2 * j].w));
            fma2(d0, qu[4 * j + 2], pack2(zf[2 * j + 1].x, zf[2 * j + 1].y));
            fma2(d1, qu[4 * j + 3], pack2(zf[2 * j + 1].z, zf[2 * j + 1].w));
        }
        float2 e0 = unpack2(d0), e1 = unpack2(d1);
        float l = (e0.x + e0.y) + (e1.x + e1.y);
        float p;
        asm("ex2.approx.f32 %0, %1;" : "=f"(p) : "f"(l * scale));
        denom += p;
        ull p2 = pack2(p, p);
#pragma unroll
        for (int j = 0; j < 8; j++) {
            fma2(outp[2 * j],     p2, pack2(zf[j].x, zf[j].y));
            fma2(outp[2 * j + 1], p2, pack2(zf[j].z, zf[j].w));
        }
    }

    float inv = __fdividef(1.f, denom);
    int orow = ((b * SEG + s) * 8 + v) * 256 + h * DQ;
#pragma unroll
    for (int j = 0; j < 8; j++) {
        float2 a = unpack2(outp[2 * j]);
        float2 c = unpack2(outp[2 * j + 1]);
        float4 o = { a.x * inv, a.y * inv, c.x * inv, c.y * inv };
        *(float4*)&g_att[orow + j * 4] = o;
    }
}

// ---------------------------------------------------------------------------
// LayerNorm over last dim (256), in place on d_out. One warp per row.
// ---------------------------------------------------------------------------
__global__ __launch_bounds__(256) void ln_kernel(
    float* __restrict__ y, const float* __restrict__ gamma,
    const float* __restrict__ beta)
{
    int warp = threadIdx.x >> 5;
    int lane = threadIdx.x & 31;
    int row = blockIdx.x * 8 + warp;

    float* p = y + (size_t)row * 256;
    float4 v0 = *(const float4*)&p[lane * 4];
    float4 v1 = *(const float4*)&p[128 + lane * 4];

    float sum = v0.x + v0.y + v0.z + v0.w + v1.x + v1.y + v1.z + v1.w;
    float sq  = v0.x * v0.x + v0.y * v0.y + v0.z * v0.z + v0.w * v0.w
              + v1.x * v1.x + v1.y * v1.y + v1.z * v1.z + v1.w * v1.w;
#pragma unroll
    for (int o = 16; o > 0; o >>= 1) {
        sum += __shfl_xor_sync(0xffffffffu, sum, o);
        sq  += __shfl_xor_sync(0xffffffffu, sq, o);
    }
    float mu = sum * (1.f / 256.f);
    float var = sq * (1.f / 256.f) - mu * mu;
    float rs = rsqrtf(var + 1e-5f);

    float4 g0 = *(const float4*)&gamma[lane * 4];
    float4 g1 = *(const float4*)&gamma[128 + lane * 4];
    float4 b0 = *(const float4*)&beta[lane * 4];
    float4 b1 = *(const float4*)&beta[128 + lane * 4];

    float4 o0, o1;
    o0.x = (v0.x - mu) * rs * g0.x + b0.x;
    o0.y = (v0.y - mu) * rs * g0.y + b0.y;
    o0.z = (v0.z - mu) * rs * g0.z + b0.z;
    o0.w = (v0.w - mu) * rs * g0.w + b0.w;
    o1.x = (v1.x - mu) * rs * g1.x + b1.x;
    o1.y = (v1.y - mu) * rs * g1.y + b1.y;
    o1.z = (v1.z - mu) * rs * g1.z + b1.z;
    o1.w = (v1.w - mu) * rs * g1.w + b1.w;

    *(float4*)&p[lane * 4] = o0;
    *(float4*)&p[128 + lane * 4] = o1;
}

// ---------------------------------------------------------------------------

extern "C" void kernel_launch(void* const* d_in, const int* in_sizes, int n_in,
                              void* d_out, int out_size)
{
    const float* x     = (const float*)d_in[0];
    const float* z     = (const float*)d_in[1];
    const float* wq    = (const float*)d_in[2];
    const float* wqb   = (const float*)d_in[3];
    const float* fcw   = (const float*)d_in[4];
    const float* fcb   = (const float*)d_in[5];
    const float* gamma = (const float*)d_in[6];
    const float* beta  = (const float*)d_in[7];
    float* y = (float*)d_out;

    const int attn_smem = (SEG * DQ + SEG * 36) * (int)sizeof(float); // 136 KB
    cudaFuncSetAttribute(attn_kernel,
                         cudaFuncAttributeMaxDynamicSharedMemorySize, attn_smem);

    dim3 ggrid(2, 128);  // cols/128, rows/128
    gemm128<0><<<ggrid, 256>>>(x, wq, wqb, nullptr, nullptr);
    attn_kernel<<<256, 512, attn_smem>>>(z);
    gemm128<1><<<ggrid, 256>>>(nullptr, fcw, fcb, x, y);
    ln_kernel<<<NTOK / 8, 256>>>(y, gamma, beta);
}

// round 2
// speedup vs baseline: 2.3632x; 2.3632x over previous
#include <cuda_runtime.h>
#include <cuda_bf16.h>
#include <cstdint>

// ---------------------------------------------------------------------------
// bs=4 seg=512 nv=8 h=8 dq=32 din=256; tokens=16384, groups=256
// All matmuls on tensor cores (mma.sync m16n8k16 bf16) with hi/lo fp32 split:
//   a*b ~= ah*bh + ah*bl + al*bh   (drop lo*lo, ~2^-16 rel err)
// ---------------------------------------------------------------------------

#define NTOK 16384
#define SEG  512
#define DQ   32
#define NG   256

__device__ __nv_bfloat16 g_qhi[NG * SEG * DQ];
__device__ __nv_bfloat16 g_qlo[NG * SEG * DQ];
__device__ __nv_bfloat16 g_zhi[NG * SEG * DQ];
__device__ __nv_bfloat16 g_zlo[NG * SEG * DQ];
__device__ float g_att[NTOK * 256];

// ---------------- helpers ----------------
__device__ __forceinline__ uint32_t sptr(const void* p) {
    return (uint32_t)__cvta_generic_to_shared(p);
}
__device__ __forceinline__ void ldsm4(uint32_t& r0, uint32_t& r1, uint32_t& r2,
                                      uint32_t& r3, uint32_t a) {
    asm volatile("ldmatrix.sync.aligned.m8n8.x4.shared.b16 {%0,%1,%2,%3}, [%4];"
                 : "=r"(r0), "=r"(r1), "=r"(r2), "=r"(r3) : "r"(a));
}
__device__ __forceinline__ void ldsm4t(uint32_t& r0, uint32_t& r1, uint32_t& r2,
                                       uint32_t& r3, uint32_t a) {
    asm volatile("ldmatrix.sync.aligned.m8n8.x4.trans.shared.b16 {%0,%1,%2,%3}, [%4];"
                 : "=r"(r0), "=r"(r1), "=r"(r2), "=r"(r3) : "r"(a));
}
__device__ __forceinline__ void mma16816(float* d, const uint32_t* a,
                                         uint32_t b0, uint32_t b1) {
    asm volatile(
        "mma.sync.aligned.m16n8k16.row.col.f32.bf16.bf16.f32 "
        "{%0,%1,%2,%3}, {%4,%5,%6,%7}, {%8,%9}, {%0,%1,%2,%3};"
        : "+f"(d[0]), "+f"(d[1]), "+f"(d[2]), "+f"(d[3])
        : "r"(a[0]), "r"(a[1]), "r"(a[2]), "r"(a[3]), "r"(b0), "r"(b1));
}
// split two fp32 into packed bf16 hi pair + lo pair
__device__ __forceinline__ void split2(float x, float y, uint32_t& hi, uint32_t& lo) {
    __nv_bfloat162 h = __floats2bfloat162_rn(x, y);
    float hx = __bfloat162float(h.x), hy = __bfloat162float(h.y);
    __nv_bfloat162 l = __floats2bfloat162_rn(x - hx, y - hy);
    hi = *(uint32_t*)&h;
    lo = *(uint32_t*)&l;
}
__device__ __forceinline__ float ex2f(float x) {
    float r;
    asm("ex2.approx.f32 %0, %1;" : "=f"(r) : "f"(x));
    return r;
}

// ---------------- z -> bf16 hi/lo planes ----------------
__global__ __launch_bounds__(256) void zsplit(const float* __restrict__ z) {
    int i = blockIdx.x * 256 + threadIdx.x;  // per float4
    float4 v = ((const float4*)z)[i];
    uint32_t h0, l0, h1, l1;
    split2(v.x, v.y, h0, l0);
    split2(v.z, v.w, h1, l1);
    ((uint2*)g_zhi)[i] = make_uint2(h0, h1);
    ((uint2*)g_zlo)[i] = make_uint2(l0, l1);
}

// ---------------------------------------------------------------------------
// GEMM: C[16384,256] = A[16384,256] @ W^T[256,256] (+bias)(+resid)
// CTA 128x128, 8 warps (2x4), warp tile 64x32. BK=32.
// MODE 0: A=x,     out -> g_qhi/g_qlo in per-group layout
// MODE 1: A=g_att, out -> Cp (fp32) = acc + bias + resid
// ---------------------------------------------------------------------------
template <int MODE>
__global__ __launch_bounds__(256) void gemm_mma(
    const float* __restrict__ Ax, const float* __restrict__ Wm,
    const float* __restrict__ bias, const float* __restrict__ resid,
    float* __restrict__ Cp)
{
    __shared__ __align__(16) __nv_bfloat16 Ah[128][40];
    __shared__ __align__(16) __nv_bfloat16 Al[128][40];
    __shared__ __align__(16) __nv_bfloat16 Wh[128][40];
    __shared__ __align__(16) __nv_bfloat16 Wl[128][40];

    const float* A = (MODE == 0) ? Ax : g_att;
    const int rb = blockIdx.y * 128, cb = blockIdx.x * 128;
    const int tid = threadIdx.x, lane = tid & 31, w = tid >> 5;
    const int wm = w & 1, wn = w >> 1;

    float acc[4][4][4];
#pragma unroll
    for (int i = 0; i < 4; i++)
#pragma unroll
        for (int j = 0; j < 4; j++)
#pragma unroll
            for (int k = 0; k < 4; k++) acc[i][j][k] = 0.f;

#pragma unroll 1
    for (int kt = 0; kt < 256; kt += 32) {
#pragma unroll
        for (int u = 0; u < 4; u++) {
            int idx = tid + u * 256;       // 1024 float4 slots
            int row = idx >> 3, kq = idx & 7;
            float4 a = *(const float4*)&A[(size_t)(rb + row) * 256 + kt + kq * 4];
            uint32_t h0, l0, h1, l1;
            split2(a.x, a.y, h0, l0);
            split2(a.z, a.w, h1, l1);
            *(uint2*)&Ah[row][kq * 4] = make_uint2(h0, h1);
            *(uint2*)&Al[row][kq * 4] = make_uint2(l0, l1);
            float4 b = *(const float4*)&Wm[(size_t)(cb + row) * 256 + kt + kq * 4];
            split2(b.x, b.y, h0, l0);
            split2(b.z, b.w, h1, l1);
            *(uint2*)&Wh[row][kq * 4] = make_uint2(h0, h1);
            *(uint2*)&Wl[row][kq * 4] = make_uint2(l0, l1);
        }
        __syncthreads();

#pragma unroll
        for (int ks = 0; ks < 2; ks++) {
            const int k0 = ks * 16;
            uint32_t ah[4][4], al[4][4];
#pragma unroll
            for (int mt = 0; mt < 4; mt++) {
                int row = wm * 64 + mt * 16 + (lane & 15);
                int kk = k0 + (lane >> 4) * 8;
                ldsm4(ah[mt][0], ah[mt][1], ah[mt][2], ah[mt][3], sptr(&Ah[row][kk]));
                ldsm4(al[mt][0], al[mt][1], al[mt][2], al[mt][3], sptr(&Al[row][kk]));
            }
            uint32_t bh[2][4], bl[2][4];
#pragma unroll
            for (int p = 0; p < 2; p++) {
                int row = wn * 32 + p * 16 + ((lane >> 4) << 3) + (lane & 7);
                int kk = k0 + ((lane >> 3) & 1) * 8;
                ldsm4(bh[p][0], bh[p][1], bh[p][2], bh[p][3], sptr(&Wh[row][kk]));
                ldsm4(bl[p][0], bl[p][1], bl[p][2], bl[p][3], sptr(&Wl[row][kk]));
            }
#pragma unroll
            for (int mt = 0; mt < 4; mt++)
#pragma unroll
                for (int nt = 0; nt < 4; nt++) {
                    int p = nt >> 1, q = (nt & 1) * 2;
                    mma16816(acc[mt][nt], ah[mt], bh[p][q], bh[p][q + 1]);
                    mma16816(acc[mt][nt], ah[mt], bl[p][q], bl[p][q + 1]);
                    mma16816(acc[mt][nt], al[mt], bh[p][q], bh[p][q + 1]);
                }
        }
        __syncthreads();
    }

    // epilogue
#pragma unroll
    for (int mt = 0; mt < 4; mt++) {
#pragma unroll
        for (int nt = 0; nt < 4; nt++) {
            int col = cb + wn * 32 + nt * 8 + 2 * (lane & 3);
            int r0 = rb + wm * 64 + mt * 16 + (lane >> 2);
            float v0 = acc[mt][nt][0] + bias[col];
            float v1 = acc[mt][nt][1] + bias[col + 1];
            float v2 = acc[mt][nt][2] + bias[col];
            float v3 = acc[mt][nt][3] + bias[col + 1];
            if (MODE == 0) {
                int h = col >> 5, d = col & 31;
                {
                    int b = r0 >> 12, s = (r0 >> 3) & 511, vv = r0 & 7;
                    int dst = (((h << 3) + vv) * 4 + b) * (SEG * DQ) + s * DQ + d;
                    uint32_t hh, ll;
                    split2(v0, v1, hh, ll);
                    *(uint32_t*)&g_qhi[dst] = hh;
                    *(uint32_t*)&g_qlo[dst] = ll;
                }
                {
                    int r1 = r0 + 8;
                    int b = r1 >> 12, s = (r1 >> 3) & 511, vv = r1 & 7;
                    int dst = (((h << 3) + vv) * 4 + b) * (SEG * DQ) + s * DQ + d;
                    uint32_t hh, ll;
                    split2(v2, v3, hh, ll);
                    *(uint32_t*)&g_qhi[dst] = hh;
                    *(uint32_t*)&g_qlo[dst] = ll;
                }
            } else {
                float2 ra = *(const float2*)&resid[(size_t)r0 * 256 + col];
                float2 rbv = *(const float2*)&resid[(size_t)(r0 + 8) * 256 + col];
                float2 o0 = { v0 + ra.x, v1 + ra.y };
                float2 o1 = { v2 + rbv.x, v3 + rbv.y };
                *(float2*)&Cp[(size_t)r0 * 256 + col] = o0;
                *(float2*)&Cp[(size_t)(r0 + 8) * 256 + col] = o1;
            }
        }
    }
}

// ---------------------------------------------------------------------------
// Attention: 1 CTA per group, 512 threads (16 warps x 32 query rows).
// Z hi/lo staged in smem once (read-only; no per-chunk syncs).
// Nc=16 KV chunk: MMA1 (S=Q Z^T) -> ex2 -> P frags in regs -> MMA2 (O += P Z).
// ---------------------------------------------------------------------------
__global__ __launch_bounds__(512) void attn_mma() {
    extern __shared__ __align__(16) __nv_bfloat16 zsm[];
    __nv_bfloat16* zh = zsm;              // [512][40]
    __nv_bfloat16* zl = zsm + 512 * 40;   // [512][40]

    const int g = blockIdx.x;
    const int tid = threadIdx.x, lane = tid & 31, w = tid >> 5;
    const int h = g >> 5, v = (g >> 2) & 7, b = g & 3;

    const __nv_bfloat16* zph = g_zhi + (size_t)g * SEG * DQ;
    const __nv_bfloat16* zpl = g_zlo + (size_t)g * SEG * DQ;
#pragma unroll
    for (int u = 0; u < 4; u++) {
        int idx = tid + u * 512;
        int row = idx >> 2, qq = idx & 3;
        *(uint4*)&zh[row * 40 + qq * 8] = *(const uint4*)&zph[row * 32 + qq * 8];
        *(uint4*)&zl[row * 40 + qq * 8] = *(const uint4*)&zpl[row * 32 + qq * 8];
    }

    // preload Q fragments (rows m0..m0+31)
    const __nv_bfloat16* qph = g_qhi + (size_t)g * SEG * DQ;
    const __nv_bfloat16* qpl = g_qlo + (size_t)g * SEG * DQ;
    const int m0 = w * 32;
    uint32_t qfh[2][2][4], qfl[2][2][4];
#pragma unroll
    for (int mt = 0; mt < 2; mt++)
#pragma unroll
        for (int ks = 0; ks < 2; ks++) {
            int row = m0 + mt * 16 + (lane >> 2);
            int kk = ks * 16 + 2 * (lane & 3);
            qfh[mt][ks][0] = *(const uint32_t*)&qph[row * 32 + kk];
            qfh[mt][ks][1] = *(const uint32_t*)&qph[(row + 8) * 32 + kk];
            qfh[mt][ks][2] = *(const uint32_t*)&qph[row * 32 + kk + 8];
            qfh[mt][ks][3] = *(const uint32_t*)&qph[(row + 8) * 32 + kk + 8];
            qfl[mt][ks][0] = *(const uint32_t*)&qpl[row * 32 + kk];
            qfl[mt][ks][1] = *(const uint32_t*)&qpl[(row + 8) * 32 + kk];
            qfl[mt][ks][2] = *(const uint32_t*)&qpl[row * 32 + kk + 8];
            qfl[mt][ks][3] = *(const uint32_t*)&qpl[(row + 8) * 32 + kk + 8];
        }

    float o[2][4][4];
#pragma unroll
    for (int i = 0; i < 2; i++)
#pragma unroll
        for (int j = 0; j < 4; j++)
#pragma unroll
            for (int k = 0; k < 4; k++) o[i][j][k] = 0.f;
    float dn[2][2] = {{0.f, 0.f}, {0.f, 0.f}};

    __syncthreads();

    const float scale = 0.2550353055731662f;  // log2(e)/sqrt(32)

#pragma unroll 1
    for (int ct = 0; ct < 32; ct++) {
        const int t0 = ct * 16;
        float s[2][2][4];
#pragma unroll
        for (int i = 0; i < 2; i++)
#pragma unroll
            for (int j = 0; j < 2; j++)
#pragma unroll
                for (int k = 0; k < 4; k++) s[i][j][k] = 0.f;

        // MMA1: S = Q Z^T   (B from Z, non-trans)
#pragma unroll
        for (int ks = 0; ks < 2; ks++) {
            int zr = t0 + ((lane >> 4) << 3) + (lane & 7);
            int zk = ks * 16 + ((lane >> 3) & 1) * 8;
            uint32_t zbh[4], zbl[4];
            ldsm4(zbh[0], zbh[1], zbh[2], zbh[3], sptr(&zh[zr * 40 + zk]));
            ldsm4(zbl[0], zbl[1], zbl[2], zbl[3], sptr(&zl[zr * 40 + zk]));
#pragma unroll
            for (int mt = 0; mt < 2; mt++)
#pragma unroll
                for (int nt = 0; nt < 2; nt++) {
                    mma16816(s[mt][nt], qfh[mt][ks], zbh[nt * 2], zbh[nt * 2 + 1]);
                    mma16816(s[mt][nt], qfh[mt][ks], zbl[nt * 2], zbl[nt * 2 + 1]);
                    mma16816(s[mt][nt], qfl[mt][ks], zbh[nt * 2], zbh[nt * 2 + 1]);
                }
        }

        // softmax numerator + pack P to bf16 hi/lo A-fragments
        uint32_t pah[2][4], pal[2][4];
#pragma unroll
        for (int mt = 0; mt < 2; mt++)
#pragma unroll
            for (int nt = 0; nt < 2; nt++) {
                float p0 = ex2f(s[mt][nt][0] * scale);
                float p1 = ex2f(s[mt][nt][1] * scale);
                float p2 = ex2f(s[mt][nt][2] * scale);
                float p3 = ex2f(s[mt][nt][3] * scale);
                dn[mt][0] += p0 + p1;
                dn[mt][1] += p2 + p3;
                split2(p0, p1, pah[mt][nt * 2], pal[mt][nt * 2]);
                split2(p2, p3, pah[mt][nt * 2 + 1], pal[mt][nt * 2 + 1]);
            }

        // MMA2: O += P Z   (B from Z, trans)
#pragma unroll
        for (int dp = 0; dp < 2; dp++) {
            int zr = t0 + (((lane >> 3) & 1) << 3) + (lane & 7);
            int zc = dp * 16 + (lane >> 4) * 8;
            uint32_t zth[4], ztl[4];
            ldsm4t(zth[0], zth[1], zth[2], zth[3], sptr(&zh[zr * 40 + zc]));
            ldsm4t(ztl[0], ztl[1], ztl[2], ztl[3], sptr(&zl[zr * 40 + zc]));
#pragma unroll
            for (int mt = 0; mt < 2; mt++)
#pragma unroll
                for (int nt = 0; nt < 2; nt++) {
                    int n = dp * 2 + nt;
                    mma16816(o[mt][n], pah[mt], zth[nt * 2], zth[nt * 2 + 1]);
                    mma16816(o[mt][n], pah[mt], ztl[nt * 2], ztl[nt * 2 + 1]);
                    mma16816(o[mt][n], pal[mt], zth[nt * 2], zth[nt * 2 + 1]);
                }
        }
    }

    // finish denominators (reduce over the 4-lane t-group)
    float inv[2][2];
#pragma unroll
    for (int mt = 0; mt < 2; mt++)
#pragma unroll
        for (int rh = 0; rh < 2; rh++) {
            float d = dn[mt][rh];
            d += __shfl_xor_sync(0xffffffffu, d, 1);
            d += __shfl_xor_sync(0xffffffffu, d, 2);
            inv[mt][rh] = __fdividef(1.f, d);
        }

    // store O to token-major g_att
#pragma unroll
    for (int mt = 0; mt < 2; mt++) {
        int s0 = m0 + mt * 16 + (lane >> 2);
        int r0 = ((b * SEG + s0) * 8) + v;
        int r1 = ((b * SEG + s0 + 8) * 8) + v;
#pragma unroll
        for (int n = 0; n < 4; n++) {
            int col = h * 32 + n * 8 + 2 * (lane & 3);
            float2 w0 = { o[mt][n][0] * inv[mt][0], o[mt][n][1] * inv[mt][0] };
            float2 w1 = { o[mt][n][2] * inv[mt][1], o[mt][n][3] * inv[mt][1] };
            *(float2*)&g_att[(size_t)r0 * 256 + col] = w0;
            *(float2*)&g_att[(size_t)r1 * 256 + col] = w1;
        }
    }
}

// ---------------- LayerNorm (in place on d_out) ----------------
__global__ __launch_bounds__(256) void ln_kernel(
    float* __restrict__ y, const float* __restrict__ gamma,
    const float* __restrict__ beta)
{
    int warp = threadIdx.x >> 5;
    int lane = threadIdx.x & 31;
    int row = blockIdx.x * 8 + warp;

    float* p = y + (size_t)row * 256;
    float4 v0 = *(const float4*)&p[lane * 4];
    float4 v1 = *(const float4*)&p[128 + lane * 4];

    float sum = v0.x + v0.y + v0.z + v0.w + v1.x + v1.y + v1.z + v1.w;
    float sq  = v0.x * v0.x + v0.y * v0.y + v0.z * v0.z + v0.w * v0.w
              + v1.x * v1.x + v1.y * v1.y + v1.z * v1.z + v1.w * v1.w;
#pragma unroll
    for (int o = 16; o > 0; o >>= 1) {
        sum += __shfl_xor_sync(0xffffffffu, sum, o);
        sq  += __shfl_xor_sync(0xffffffffu, sq, o);
    }
    float mu = sum * (1.f / 256.f);
    float var = sq * (1.f / 256.f) - mu * mu;
    float rs = rsqrtf(var + 1e-5f);

    float4 g0 = *(const float4*)&gamma[lane * 4];
    float4 g1 = *(const float4*)&gamma[128 + lane * 4];
    float4 b0 = *(const float4*)&beta[lane * 4];
    float4 b1 = *(const float4*)&beta[128 + lane * 4];

    float4 o0, o1;
    o0.x = (v0.x - mu) * rs * g0.x + b0.x;
    o0.y = (v0.y - mu) * rs * g0.y + b0.y;
    o0.z = (v0.z - mu) * rs * g0.z + b0.z;
    o0.w = (v0.w - mu) * rs * g0.w + b0.w;
    o1.x = (v1.x - mu) * rs * g1.x + b1.x;
    o1.y = (v1.y - mu) * rs * g1.y + b1.y;
    o1.z = (v1.z - mu) * rs * g1.z + b1.z;
    o1.w = (v1.w - mu) * rs * g1.w + b1.w;

    *(float4*)&p[lane * 4] = o0;
    *(float4*)&p[128 + lane * 4] = o1;
}

// ---------------------------------------------------------------------------

extern "C" void kernel_launch(void* const* d_in, const int* in_sizes, int n_in,
                              void* d_out, int out_size)
{
    const float* x     = (const float*)d_in[0];
    const float* z     = (const float*)d_in[1];
    const float* wq    = (const float*)d_in[2];
    const float* wqb   = (const float*)d_in[3];
    const float* fcw   = (const float*)d_in[4];
    const float* fcb   = (const float*)d_in[5];
    const float* gamma = (const float*)d_in[6];
    const float* beta  = (const float*)d_in[7];
    float* y = (float*)d_out;

    const int attn_smem = 2 * 512 * 40 * (int)sizeof(__nv_bfloat16);  // 81920 B
    cudaFuncSetAttribute(attn_mma,
                         cudaFuncAttributeMaxDynamicSharedMemorySize, attn_smem);

    zsplit<<<NG * SEG * DQ / 4 / 256, 256>>>(z);
    dim3 ggrid(2, 128);
    gemm_mma<0><<<ggrid, 256>>>(x, wq, wqb, nullptr, nullptr);
    attn_mma<<<NG, 512, attn_smem>>>();
    gemm_mma<1><<<ggrid, 256>>>(nullptr, fcw, fcb, x, y);
    ln_kernel<<<NTOK / 8, 256>>>(y, gamma, beta);
}

// round 3
// speedup vs baseline: 2.9257x; 1.2380x over previous
#include <cuda_runtime.h>
#include <cuda_bf16.h>
#include <cstdint>

// ---------------------------------------------------------------------------
// bs=4 seg=512 nv=8 h=8 dq=32 din=256; tokens=16384, groups=256
// Tensor-core everything (mma.sync m16n8k16 bf16, hi/lo fp32 split).
//  - prep: z + both weight matrices -> bf16 hi/lo planes
//  - gemm0: q = (x@WqT + b) * softmax_scale -> per-group bf16 hi/lo planes
//  - attn : pipelined MMA1 / ex2 / MMA2, P kept hi-only
//  - gemm1: fc + bias + residual + fused LayerNorm -> d_out
// ---------------------------------------------------------------------------

#define NTOK 16384
#define SEG  512
#define DQ   32
#define NG   256
#define SCALE 0.2550353055731662f   // log2(e)/sqrt(32)

typedef __nv_bfloat16 bf16;

__device__ bf16 g_qhi[NG * SEG * DQ];
__device__ bf16 g_qlo[NG * SEG * DQ];
__device__ bf16 g_zhi[NG * SEG * DQ];
__device__ bf16 g_zlo[NG * SEG * DQ];
__device__ bf16 g_wqh[256 * 256];
__device__ bf16 g_wql[256 * 256];
__device__ bf16 g_fh[256 * 256];
__device__ bf16 g_fl[256 * 256];
__device__ float g_att[NTOK * 256];

// ---------------- helpers ----------------
__device__ __forceinline__ uint32_t sptr(const void* p) {
    return (uint32_t)__cvta_generic_to_shared(p);
}
__device__ __forceinline__ void ldsm4(uint32_t& r0, uint32_t& r1, uint32_t& r2,
                                      uint32_t& r3, uint32_t a) {
    asm volatile("ldmatrix.sync.aligned.m8n8.x4.shared.b16 {%0,%1,%2,%3}, [%4];"
                 : "=r"(r0), "=r"(r1), "=r"(r2), "=r"(r3) : "r"(a));
}
__device__ __forceinline__ void ldsm4t(uint32_t& r0, uint32_t& r1, uint32_t& r2,
                                       uint32_t& r3, uint32_t a) {
    asm volatile("ldmatrix.sync.aligned.m8n8.x4.trans.shared.b16 {%0,%1,%2,%3}, [%4];"
                 : "=r"(r0), "=r"(r1), "=r"(r2), "=r"(r3) : "r"(a));
}
__device__ __forceinline__ void mma16816(float* d, const uint32_t* a,
                                         uint32_t b0, uint32_t b1) {
    asm volatile(
        "mma.sync.aligned.m16n8k16.row.col.f32.bf16.bf16.f32 "
        "{%0,%1,%2,%3}, {%4,%5,%6,%7}, {%8,%9}, {%0,%1,%2,%3};"
        : "+f"(d[0]), "+f"(d[1]), "+f"(d[2]), "+f"(d[3])
        : "r"(a[0]), "r"(a[1]), "r"(a[2]), "r"(a[3]), "r"(b0), "r"(b1));
}
__device__ __forceinline__ void split2(float x, float y, uint32_t& hi, uint32_t& lo) {
    __nv_bfloat162 h = __floats2bfloat162_rn(x, y);
    float hx = __bfloat162float(h.x), hy = __bfloat162float(h.y);
    __nv_bfloat162 l = __floats2bfloat162_rn(x - hx, y - hy);
    hi = *(uint32_t*)&h;
    lo = *(uint32_t*)&l;
}
__device__ __forceinline__ uint32_t pack_bf16(float x, float y) {
    __nv_bfloat162 h = __floats2bfloat162_rn(x, y);
    return *(uint32_t*)&h;
}
__device__ __forceinline__ float ex2f(float x) {
    float r;
    asm("ex2.approx.f32 %0, %1;" : "=f"(r) : "f"(x));
    return r;
}
__device__ __forceinline__ void cpasync16(uint32_t dst, const void* src) {
    asm volatile("cp.async.ca.shared.global [%0], [%1], 16;" :: "r"(dst), "l"(src));
}

// ---------------- prep: split z + weights into bf16 hi/lo planes ----------
__global__ __launch_bounds__(256) void prep(const float* __restrict__ z,
                                            const float* __restrict__ wq,
                                            const float* __restrict__ fcw) {
    int blk = blockIdx.x;
    const float* src;
    bf16 *dh, *dl;
    int i;
    if (blk < 4096) { src = z; dh = g_zhi; dl = g_zlo; i = blk * 256 + threadIdx.x; }
    else if (blk < 4160) { src = wq; dh = g_wqh; dl = g_wql; i = (blk - 4096) * 256 + threadIdx.x; }
    else { src = fcw; dh = g_fh; dl = g_fl; i = (blk - 4160) * 256 + threadIdx.x; }
    float4 v = ((const float4*)src)[i];
    uint32_t h0, l0, h1, l1;
    split2(v.x, v.y, h0, l0);
    split2(v.z, v.w, h1, l1);
    ((uint2*)dh)[i] = make_uint2(h0, h1);
    ((uint2*)dl)[i] = make_uint2(l0, l1);
}

// ---------------------------------------------------------------------------
// GEMM: C[16384,256] = A[16384,256] @ W^T (+bias...). Tile 128 rows x 256 cols,
// 512 threads (16 warps: wm in {0,1} x wn in {0..7}), warp tile 64x32, BK=32,
// double-buffered (W via cp.async from pre-split planes; A via reg prefetch).
// MODE 0: A=x, out = (acc+bias)*SCALE -> g_qhi/g_qlo per-group layout
// MODE 1: A=g_att, out = LN(acc + bias + resid) -> Cp
// ---------------------------------------------------------------------------
#define GSM_A  (128 * 40)            // bf16 elems per A plane per buf
#define GSM_W  (256 * 40)
#define GSMEM_BYTES ((2 * 2 * GSM_A + 2 * 2 * GSM_W) * 2)

template <int MODE>
__global__ __launch_bounds__(512, 1) void gemm_mma(
    const float* __restrict__ Ax, const bf16* __restrict__ Wh_g,
    const bf16* __restrict__ Wl_g, const float* __restrict__ bias,
    const float* __restrict__ resid, const float* __restrict__ gamma,
    const float* __restrict__ beta, float* __restrict__ Cp)
{
    extern __shared__ char smem_raw[];
    bf16* Ah = (bf16*)smem_raw;           // [2][128][40]
    bf16* Al = Ah + 2 * GSM_A;
    bf16* Wh = Al + 2 * GSM_A;            // [2][256][40]
    bf16* Wl = Wh + 2 * GSM_W;

    const float* A = (MODE == 0) ? Ax : g_att;
    const int rb = blockIdx.x * 128;
    const int tid = threadIdx.x, lane = tid & 31, w = tid >> 5;
    const int wm = w & 1, wn = w >> 1;

    // per-thread load coords
    const int a_row = tid >> 3, a_kq = (tid & 7) * 4;          // +64 rows for u=1
    const int w_i0 = tid;                                       // 4 uint4 slots

    auto issueW = [&](int kt, int buf) {
#pragma unroll
        for (int u = 0; u < 4; u++) {
            int idx = w_i0 + u * 512;
            int plane = idx >> 10, r = (idx >> 2) & 255, kq = (idx & 3) * 8;
            const bf16* srcp = (plane ? Wl_g : Wh_g) + r * 256 + kt * 32 + kq;
            bf16* dstp = (plane ? Wl : Wh) + buf * GSM_W + r * 40 + kq;
            cpasync16(sptr(dstp), srcp);
        }
        asm volatile("cp.async.commit_group;");
    };
    auto loadA = [&](int kt, float4& a0, float4& a1) {
        a0 = *(const float4*)&A[(size_t)(rb + a_row) * 256 + kt * 32 + a_kq];
        a1 = *(const float4*)&A[(size_t)(rb + a_row + 64) * 256 + kt * 32 + a_kq];
    };
    auto storeA = [&](int buf, float4 a0, float4 a1) {
        uint32_t h0, l0, h1, l1;
        split2(a0.x, a0.y, h0, l0);
        split2(a0.z, a0.w, h1, l1);
        *(uint2*)&Ah[buf * GSM_A + a_row * 40 + a_kq] = make_uint2(h0, h1);
        *(uint2*)&Al[buf * GSM_A + a_row * 40 + a_kq] = make_uint2(l0, l1);
        split2(a1.x, a1.y, h0, l0);
        split2(a1.z, a1.w, h1, l1);
        *(uint2*)&Ah[buf * GSM_A + (a_row + 64) * 40 + a_kq] = make_uint2(h0, h1);
        *(uint2*)&Al[buf * GSM_A + (a_row + 64) * 40 + a_kq] = make_uint2(l0, l1);
    };

    float acc[4][4][4];
#pragma unroll
    for (int i = 0; i < 4; i++)
#pragma unroll
        for (int j = 0; j < 4; j++)
#pragma unroll
            for (int k = 0; k < 4; k++) acc[i][j][k] = 0.f;

    // prologue: tile 0
    {
        issueW(0, 0);
        float4 a0, a1;
        loadA(0, a0, a1);
        storeA(0, a0, a1);
        asm volatile("cp.async.wait_group 0;");
    }
    __syncthreads();

#pragma unroll 1
    for (int kt = 0; kt < 8; kt++) {
        const int buf = kt & 1;
        float4 a0, a1;
        if (kt < 7) {
            issueW(kt + 1, buf ^ 1);
            loadA(kt + 1, a0, a1);
        }
        // compute current buffer
#pragma unroll
        for (int ks = 0; ks < 2; ks++) {
            uint32_t bh[2][4], bl[2][4];
#pragma unroll
            for (int p = 0; p < 2; p++) {
                int row = wn * 32 + p * 16 + ((lane >> 4) << 3) + (lane & 7);
                int kk = ks * 16 + ((lane >> 3) & 1) * 8;
                ldsm4(bh[p][0], bh[p][1], bh[p][2], bh[p][3],
                      sptr(&Wh[buf * GSM_W + row * 40 + kk]));
                ldsm4(bl[p][0], bl[p][1], bl[p][2], bl[p][3],
                      sptr(&Wl[buf * GSM_W + row * 40 + kk]));
            }
#pragma unroll
            for (int mt = 0; mt < 4; mt++) {
                int row = wm * 64 + mt * 16 + (lane & 15);
                int kk = ks * 16 + (lane >> 4) * 8;
                uint32_t ah[4], al[4];
                ldsm4(ah[0], ah[1], ah[2], ah[3], sptr(&Ah[buf * GSM_A + row * 40 + kk]));
                ldsm4(al[0], al[1], al[2], al[3], sptr(&Al[buf * GSM_A + row * 40 + kk]));
#pragma unroll
                for (int nt = 0; nt < 4; nt++) {
                    int p = nt >> 1, q = (nt & 1) * 2;
                    mma16816(acc[mt][nt], ah, bh[p][q], bh[p][q + 1]);
                    mma16816(acc[mt][nt], ah, bl[p][q], bl[p][q + 1]);
                    mma16816(acc[mt][nt], al, bh[p][q], bh[p][q + 1]);
                }
            }
        }
        if (kt < 7) {
            storeA(buf ^ 1, a0, a1);
            asm volatile("cp.async.wait_group 0;");
        }
        __syncthreads();
    }

    // ---------------- epilogue ----------------
    if (MODE == 0) {
#pragma unroll
        for (int mt = 0; mt < 4; mt++) {
#pragma unroll
            for (int nt = 0; nt < 4; nt++) {
                int col = wn * 32 + nt * 8 + 2 * (lane & 3);
                int r0 = rb + wm * 64 + mt * 16 + (lane >> 2);
                float b0 = bias[col], b1 = bias[col + 1];
                float v0 = (acc[mt][nt][0] + b0) * SCALE;
                float v1 = (acc[mt][nt][1] + b1) * SCALE;
                float v2 = (acc[mt][nt][2] + b0) * SCALE;
                float v3 = (acc[mt][nt][3] + b1) * SCALE;
                int h = col >> 5, d = col & 31;
                {
                    int b = r0 >> 12, s = (r0 >> 3) & 511, vv = r0 & 7;
                    int dst = (((h << 3) + vv) * 4 + b) * (SEG * DQ) + s * DQ + d;
                    uint32_t hh, ll;
                    split2(v0, v1, hh, ll);
                    *(uint32_t*)&g_qhi[dst] = hh;
                    *(uint32_t*)&g_qlo[dst] = ll;
                }
                {
                    int r1 = r0 + 8;
                    int b = r1 >> 12, s = (r1 >> 3) & 511, vv = r1 & 7;
                    int dst = (((h << 3) + vv) * 4 + b) * (SEG * DQ) + s * DQ + d;
                    uint32_t hh, ll;
                    split2(v2, v3, hh, ll);
                    *(uint32_t*)&g_qhi[dst] = hh;
                    *(uint32_t*)&g_qlo[dst] = ll;
                }
            }
        }
    } else {
        // add bias + residual, then fused LayerNorm over the 256-wide rows
        float2* red = (float2*)smem_raw;                  // [128][8]
        float* mus = (float*)(smem_raw + 8192);           // [128]
        float* rss = (float*)(smem_raw + 8192 + 512);     // [128]

#pragma unroll
        for (int mt = 0; mt < 4; mt++) {
            float s0 = 0.f, q0 = 0.f, s1 = 0.f, q1 = 0.f;
            int rl = wm * 64 + mt * 16 + (lane >> 2);
#pragma unroll
            for (int nt = 0; nt < 4; nt++) {
                int col = wn * 32 + nt * 8 + 2 * (lane & 3);
                float b0 = bias[col], b1 = bias[col + 1];
                float2 rx0 = *(const float2*)&resid[(size_t)(rb + rl) * 256 + col];
                float2 rx1 = *(const float2*)&resid[(size_t)(rb + rl + 8) * 256 + col];
                acc[mt][nt][0] += b0 + rx0.x;
                acc[mt][nt][1] += b1 + rx0.y;
                acc[mt][nt][2] += b0 + rx1.x;
                acc[mt][nt][3] += b1 + rx1.y;
                s0 += acc[mt][nt][0] + acc[mt][nt][1];
                q0 += acc[mt][nt][0] * acc[mt][nt][0] + acc[mt][nt][1] * acc[mt][nt][1];
                s1 += acc[mt][nt][2] + acc[mt][nt][3];
                q1 += acc[mt][nt][2] * acc[mt][nt][2] + acc[mt][nt][3] * acc[mt][nt][3];
            }
#pragma unroll
            for (int o = 1; o <= 2; o <<= 1) {
                s0 += __shfl_xor_sync(0xffffffffu, s0, o);
                q0 += __shfl_xor_sync(0xffffffffu, q0, o);
                s1 += __shfl_xor_sync(0xffffffffu, s1, o);
                q1 += __shfl_xor_sync(0xffffffffu, q1, o);
            }
            if ((lane & 3) == 0) {
                red[rl * 8 + wn] = make_float2(s0, q0);
                red[(rl + 8) * 8 + wn] = make_float2(s1, q1);
            }
        }
        __syncthreads();
        if (tid < 128) {
            float s = 0.f, q = 0.f;
#pragma unroll
            for (int j = 0; j < 8; j++) {
                float2 p = red[tid * 8 + j];
                s += p.x;
                q += p.y;
            }
            float mu = s * (1.f / 256.f);
            float var = q * (1.f / 256.f) - mu * mu;
            mus[tid] = mu;
            rss[tid] = rsqrtf(var + 1e-5f);
        }
        __syncthreads();
#pragma unroll
        for (int nt = 0; nt < 4; nt++) {
            int col = wn * 32 + nt * 8 + 2 * (lane & 3);
            float g0 = gamma[col], g1 = gamma[col + 1];
            float be0 = beta[col], be1 = beta[col + 1];
#pragma unroll
            for (int mt = 0; mt < 4; mt++) {
                int rl = wm * 64 + mt * 16 + (lane >> 2);
                float mu0 = mus[rl], rs0 = rss[rl];
                float mu1 = mus[rl + 8], rs1 = rss[rl + 8];
                float2 o0 = { (acc[mt][nt][0] - mu0) * rs0 * g0 + be0,
                              (acc[mt][nt][1] - mu0) * rs0 * g1 + be1 };
                float2 o1 = { (acc[mt][nt][2] - mu1) * rs1 * g0 + be0,
                              (acc[mt][nt][3] - mu1) * rs1 * g1 + be1 };
                *(float2*)&Cp[(size_t)(rb + rl) * 256 + col] = o0;
                *(float2*)&Cp[(size_t)(rb + rl + 8) * 256 + col] = o1;
            }
        }
    }
}

// ---------------------------------------------------------------------------
// Attention: 1 CTA per group, 512 threads (16 warps x 32 query rows).
// Q prescaled by log2(e)/temp. P kept hi-only. Software-pipelined:
//   softmax(S_ct) ; S_{ct+1} = MMA1 ; O += MMA2(P_ct)
// ---------------------------------------------------------------------------
struct AttnCtx {
    bf16 *zh, *zl;
    int lane;
    uint32_t qfh[2][2][4], qfl[2][2][4];
};

__device__ __forceinline__ void attn_mma1(AttnCtx& c, int ct, float s[2][2][4]) {
#pragma unroll
    for (int i = 0; i < 2; i++)
#pragma unroll
        for (int j = 0; j < 2; j++)
#pragma unroll
            for (int k = 0; k < 4; k++) s[i][j][k] = 0.f;
    const int t0 = ct * 16;
#pragma unroll
    for (int ks = 0; ks < 2; ks++) {
        int zr = t0 + ((c.lane >> 4) << 3) + (c.lane & 7);
        int zk = ks * 16 + ((c.lane >> 3) & 1) * 8;
        uint32_t zbh[4], zbl[4];
        ldsm4(zbh[0], zbh[1], zbh[2], zbh[3], sptr(&c.zh[zr * 40 + zk]));
        ldsm4(zbl[0], zbl[1], zbl[2], zbl[3], sptr(&c.zl[zr * 40 + zk]));
#pragma unroll
        for (int mt = 0; mt < 2; mt++)
#pragma unroll
            for (int nt = 0; nt < 2; nt++) {
                mma16816(s[mt][nt], c.qfh[mt][ks], zbh[nt * 2], zbh[nt * 2 + 1]);
                mma16816(s[mt][nt], c.qfh[mt][ks], zbl[nt * 2], zbl[nt * 2 + 1]);
                mma16816(s[mt][nt], c.qfl[mt][ks], zbh[nt * 2], zbh[nt * 2 + 1]);
            }
    }
}

__device__ __forceinline__ void attn_softmax(float s[2][2][4], uint32_t pah[2][4],
                                             float dn[2][2]) {
#pragma unroll
    for (int mt = 0; mt < 2; mt++)
#pragma unroll
        for (int nt = 0; nt < 2; nt++) {
            float p0 = ex2f(s[mt][nt][0]);
            float p1 = ex2f(s[mt][nt][1]);
            float p2 = ex2f(s[mt][nt][2]);
            float p3 = ex2f(s[mt][nt][3]);
            dn[mt][0] += p0 + p1;
            dn[mt][1] += p2 + p3;
            pah[mt][nt * 2] = pack_bf16(p0, p1);
            pah[mt][nt * 2 + 1] = pack_bf16(p2, p3);
        }
}

__device__ __forceinline__ void attn_mma2(AttnCtx& c, int ct, uint32_t pah[2][4],
                                          float o[2][4][4]) {
    const int t0 = ct * 16;
#pragma unroll
    for (int dp = 0; dp < 2; dp++) {
        int zr = t0 + (((c.lane >> 3) & 1) << 3) + (c.lane & 7);
        int zc = dp * 16 + (c.lane >> 4) * 8;
        uint32_t zth[4], ztl[4];
        ldsm4t(zth[0], zth[1], zth[2], zth[3], sptr(&c.zh[zr * 40 + zc]));
        ldsm4t(ztl[0], ztl[1], ztl[2], ztl[3], sptr(&c.zl[zr * 40 + zc]));
#pragma unroll
        for (int mt = 0; mt < 2; mt++)
#pragma unroll
            for (int nt = 0; nt < 2; nt++) {
                int n = dp * 2 + nt;
                mma16816(o[mt][n], pah[mt], zth[nt * 2], zth[nt * 2 + 1]);
                mma16816(o[mt][n], pah[mt], ztl[nt * 2], ztl[nt * 2 + 1]);
            }
    }
}

__global__ __launch_bounds__(512) void attn_mma() {
    extern __shared__ __align__(16) bf16 zsm[];
    AttnCtx c;
    c.zh = zsm;
    c.zl = zsm + 512 * 40;

    const int g = blockIdx.x;
    const int tid = threadIdx.x, w = tid >> 5;
    c.lane = tid & 31;
    const int lane = c.lane;
    const int h = g >> 5, v = (g >> 2) & 7, b = g & 3;

    const bf16* zph = g_zhi + (size_t)g * SEG * DQ;
    const bf16* zpl = g_zlo + (size_t)g * SEG * DQ;
#pragma unroll
    for (int u = 0; u < 4; u++) {
        int idx = tid + u * 512;
        int row = idx >> 2, qq = idx & 3;
        *(uint4*)&c.zh[row * 40 + qq * 8] = *(const uint4*)&zph[row * 32 + qq * 8];
        *(uint4*)&c.zl[row * 40 + qq * 8] = *(const uint4*)&zpl[row * 32 + qq * 8];
    }

    const bf16* qph = g_qhi + (size_t)g * SEG * DQ;
    const bf16* qpl = g_qlo + (size_t)g * SEG * DQ;
    const int m0 = w * 32;
#pragma unroll
    for (int mt = 0; mt < 2; mt++)
#pragma unroll
        for (int ks = 0; ks < 2; ks++) {
            int row = m0 + mt * 16 + (lane >> 2);
            int kk = ks * 16 + 2 * (lane & 3);
            c.qfh[mt][ks][0] = *(const uint32_t*)&qph[row * 32 + kk];
            c.qfh[mt][ks][1] = *(const uint32_t*)&qph[(row + 8) * 32 + kk];
            c.qfh[mt][ks][2] = *(const uint32_t*)&qph[row * 32 + kk + 8];
            c.qfh[mt][ks][3] = *(const uint32_t*)&qph[(row + 8) * 32 + kk + 8];
            c.qfl[mt][ks][0] = *(const uint32_t*)&qpl[row * 32 + kk];
            c.qfl[mt][ks][1] = *(const uint32_t*)&qpl[(row + 8) * 32 + kk];
            c.qfl[mt][ks][2] = *(const uint32_t*)&qpl[row * 32 + kk + 8];
            c.qfl[mt][ks][3] = *(const uint32_t*)&qpl[(row + 8) * 32 + kk + 8];
        }

    float o[2][4][4];
#pragma unroll
    for (int i = 0; i < 2; i++)
#pragma unroll
        for (int j = 0; j < 4; j++)
#pragma unroll
            for (int k = 0; k < 4; k++) o[i][j][k] = 0.f;
    float dn[2][2] = {{0.f, 0.f}, {0.f, 0.f}};

    __syncthreads();

    float s[2][2][4];
    attn_mma1(c, 0, s);

#pragma unroll 1
    for (int ct = 0; ct < 31; ct++) {
        uint32_t pah[2][4];
        attn_softmax(s, pah, dn);
        float s2[2][2][4];
        attn_mma1(c, ct + 1, s2);
        attn_mma2(c, ct, pah, o);
#pragma unroll
        for (int i = 0; i < 2; i++)
#pragma unroll
            for (int j = 0; j < 2; j++)
#pragma unroll
                for (int k = 0; k < 4; k++) s[i][j][k] = s2[i][j][k];
    }
    {
        uint32_t pah[2][4];
        attn_softmax(s, pah, dn);
        attn_mma2(c, 31, pah, o);
    }

    float inv[2][2];
#pragma unroll
    for (int mt = 0; mt < 2; mt++)
#pragma unroll
        for (int rh = 0; rh < 2; rh++) {
            float d = dn[mt][rh];
            d += __shfl_xor_sync(0xffffffffu, d, 1);
            d += __shfl_xor_sync(0xffffffffu, d, 2);
            inv[mt][rh] = __fdividef(1.f, d);
        }

#pragma unroll
    for (int mt = 0; mt < 2; mt++) {
        int s0 = m0 + mt * 16 + (lane >> 2);
        int r0 = ((b * SEG + s0) * 8) + v;
        int r1 = ((b * SEG + s0 + 8) * 8) + v;
#pragma unroll
        for (int n = 0; n < 4; n++) {
            int col = h * 32 + n * 8 + 2 * (lane & 3);
            float2 w0 = { o[mt][n][0] * inv[mt][0], o[mt][n][1] * inv[mt][0] };
            float2 w1 = { o[mt][n][2] * inv[mt][1], o[mt][n][3] * inv[mt][1] };
            *(float2*)&g_att[(size_t)r0 * 256 + col] = w0;
            *(float2*)&g_att[(size_t)r1 * 256 + col] = w1;
        }
    }
}

// ---------------------------------------------------------------------------

extern "C" void kernel_launch(void* const* d_in, const int* in_sizes, int n_in,
                              void* d_out, int out_size)
{
    const float* x     = (const float*)d_in[0];
    const float* z     = (const float*)d_in[1];
    const float* wq    = (const float*)d_in[2];
    const float* wqb   = (const float*)d_in[3];
    const float* fcw   = (const float*)d_in[4];
    const float* fcb   = (const float*)d_in[5];
    const float* gamma = (const float*)d_in[6];
    const float* beta  = (const float*)d_in[7];
    float* y = (float*)d_out;

    static bf16 *wqh_p = nullptr, *wql_p, *fh_p, *fl_p;
    if (!wqh_p) {
        cudaGetSymbolAddress((void**)&wqh_p, g_wqh);
        cudaGetSymbolAddress((void**)&wql_p, g_wql);
        cudaGetSymbolAddress((void**)&fh_p, g_fh);
        cudaGetSymbolAddress((void**)&fl_p, g_fl);
        cudaFuncSetAttribute(gemm_mma<0>, cudaFuncAttributeMaxDynamicSharedMemorySize, GSMEM_BYTES);
        cudaFuncSetAttribute(gemm_mma<1>, cudaFuncAttributeMaxDynamicSharedMemorySize, GSMEM_BYTES);
        cudaFuncSetAttribute(attn_mma, cudaFuncAttributeMaxDynamicSharedMemorySize, 2 * 512 * 40 * 2);
    }

    prep<<<4224, 256>>>(z, wq, fcw);
    gemm_mma<0><<<128, 512, GSMEM_BYTES>>>(x, wqh_p, wql_p, wqb, nullptr, nullptr, nullptr, nullptr);
    attn_mma<<<NG, 512, 2 * 512 * 40 * 2>>>();
    gemm_mma<1><<<128, 512, GSMEM_BYTES>>>(nullptr, fh_p, fl_p, fcb, x, gamma, beta, y);
}

// round 5
// speedup vs baseline: 2.9280x; 1.0008x over previous
#include <cuda_runtime.h>
#include <cuda_bf16.h>
#include <cstdint>

// ---------------------------------------------------------------------------
// bs=4 seg=512 nv=8 h=8 dq=32 din=256; tokens=16384, groups=256
// All operands as bf16 hi/lo planes (fp32 = hi + lo, 3-term MMA).
//  prep  : x, z, Wq, fc -> hi/lo planes
//  gemm0 : q = (x@WqT + b)*log2e/temp -> per-group q planes  (128x128 tiles)
//  attn  : 2 CTAs/group; MMA1 3-term, ex2 softmax, MMA2 1-term -> o planes
//  gemm1 : fc + bias + residual + fused LayerNorm -> d_out (128x256 tiles,
//          full row per CTA so LN statistics are complete)
// ---------------------------------------------------------------------------

#define NTOK 16384
#define SEG  512
#define DQ   32
#define NG   256
#define SCALE 0.2550353055731662f   // log2(e)/sqrt(32)

typedef __nv_bfloat16 bf16;

__device__ bf16 g_qhi[NG * SEG * DQ];
__device__ bf16 g_qlo[NG * SEG * DQ];
__device__ bf16 g_zhi[NG * SEG * DQ];
__device__ bf16 g_zlo[NG * SEG * DQ];
__device__ bf16 g_xhi[NTOK * 256];
__device__ bf16 g_xlo[NTOK * 256];
__device__ bf16 g_ohi[NTOK * 256];
__device__ bf16 g_olo[NTOK * 256];
__device__ bf16 g_wqh[256 * 256];
__device__ bf16 g_wql[256 * 256];
__device__ bf16 g_fh[256 * 256];
__device__ bf16 g_fl[256 * 256];

// ---------------- helpers ----------------
__device__ __forceinline__ uint32_t sptr(const void* p) {
    return (uint32_t)__cvta_generic_to_shared(p);
}
__device__ __forceinline__ void ldsm4(uint32_t& r0, uint32_t& r1, uint32_t& r2,
                                      uint32_t& r3, uint32_t a) {
    asm volatile("ldmatrix.sync.aligned.m8n8.x4.shared.b16 {%0,%1,%2,%3}, [%4];"
                 : "=r"(r0), "=r"(r1), "=r"(r2), "=r"(r3) : "r"(a));
}
__device__ __forceinline__ void ldsm4t(uint32_t& r0, uint32_t& r1, uint32_t& r2,
                                       uint32_t& r3, uint32_t a) {
    asm volatile("ldmatrix.sync.aligned.m8n8.x4.trans.shared.b16 {%0,%1,%2,%3}, [%4];"
                 : "=r"(r0), "=r"(r1), "=r"(r2), "=r"(r3) : "r"(a));
}
__device__ __forceinline__ void mma16816(float* d, const uint32_t* a,
                                         uint32_t b0, uint32_t b1) {
    asm volatile(
        "mma.sync.aligned.m16n8k16.row.col.f32.bf16.bf16.f32 "
        "{%0,%1,%2,%3}, {%4,%5,%6,%7}, {%8,%9}, {%0,%1,%2,%3};"
        : "+f"(d[0]), "+f"(d[1]), "+f"(d[2]), "+f"(d[3])
        : "r"(a[0]), "r"(a[1]), "r"(a[2]), "r"(a[3]), "r"(b0), "r"(b1));
}
__device__ __forceinline__ void split2(float x, float y, uint32_t& hi, uint32_t& lo) {
    __nv_bfloat162 h = __floats2bfloat162_rn(x, y);
    float hx = __bfloat162float(h.x), hy = __bfloat162float(h.y);
    __nv_bfloat162 l = __floats2bfloat162_rn(x - hx, y - hy);
    hi = *(uint32_t*)&h;
    lo = *(uint32_t*)&l;
}
__device__ __forceinline__ uint32_t pack_bf16(float x, float y) {
    __nv_bfloat162 h = __floats2bfloat162_rn(x, y);
    return *(uint32_t*)&h;
}
__device__ __forceinline__ float ex2f(float x) {
    float r;
    asm("ex2.approx.f32 %0, %1;" : "=f"(r) : "f"(x));
    return r;
}
__device__ __forceinline__ void cpasync16(uint32_t dst, const void* src) {
    asm volatile("cp.async.ca.shared.global [%0], [%1], 16;" :: "r"(dst), "l"(src));
}

// ---------------- prep: split sources into bf16 hi/lo planes ----------------
__global__ __launch_bounds__(256) void prep(const float* __restrict__ z,
                                            const float* __restrict__ x,
                                            const float* __restrict__ wq,
                                            const float* __restrict__ fcw) {
    int blk = blockIdx.x;
    const float* src;
    bf16 *dh, *dl;
    int i;
    if (blk < 4096)      { src = z;   dh = g_zhi; dl = g_zlo; i = blk * 256 + threadIdx.x; }
    else if (blk < 8192) { src = x;   dh = g_xhi; dl = g_xlo; i = (blk - 4096) * 256 + threadIdx.x; }
    else if (blk < 8256) { src = wq;  dh = g_wqh; dl = g_wql; i = (blk - 8192) * 256 + threadIdx.x; }
    else                 { src = fcw; dh = g_fh;  dl = g_fl;  i = (blk - 8256) * 256 + threadIdx.x; }
    float4 v = ((const float4*)src)[i];
    uint32_t h0, l0, h1, l1;
    split2(v.x, v.y, h0, l0);
    split2(v.z, v.w, h1, l1);
    ((uint2*)dh)[i] = make_uint2(h0, h1);
    ((uint2*)dl)[i] = make_uint2(l0, l1);
}

// ---------------------------------------------------------------------------
// gemm0: q-projection. 128x128 tile, 256 thr (8 warps 2x4), BK=32,
// 2-stage cp.async, all operands pre-split bf16 planes.
// out = (acc + bias) * SCALE scattered into per-group q planes.
// ---------------------------------------------------------------------------
#define G0_P (128 * 40)
#define G0_SMEM (2 * 4 * G0_P * 2)   // 81920

__global__ __launch_bounds__(256, 2) void gemm0(
    const bf16* __restrict__ Ah_g, const bf16* __restrict__ Al_g,
    const bf16* __restrict__ Wh_g, const bf16* __restrict__ Wl_g,
    const float* __restrict__ bias)
{
    extern __shared__ char smem_raw[];
    bf16* pl[4];
    pl[0] = (bf16*)smem_raw;
    pl[1] = pl[0] + 2 * G0_P;
    pl[2] = pl[1] + 2 * G0_P;
    pl[3] = pl[2] + 2 * G0_P;

    const int rb = blockIdx.y * 128, cb = blockIdx.x * 128;
    const int tid = threadIdx.x, lane = tid & 31, w = tid >> 5;
    const int wmi = w & 1, wn = w >> 1;

    const bf16* gsrc[4] = { Ah_g, Al_g, Wh_g, Wl_g };
    const int gbase[4] = { rb, rb, cb, cb };

    auto issue = [&](int kt, int buf) {
#pragma unroll
        for (int u = 0; u < 8; u++) {
            int idx = tid + u * 256;
            int plane = idx >> 9, rem = idx & 511;
            int row = rem >> 2, q = (rem & 3) * 8;
            const bf16* srcp = gsrc[plane] + (size_t)(gbase[plane] + row) * 256 + kt * 32 + q;
            cpasync16(sptr(pl[plane] + buf * G0_P + row * 40 + q), srcp);
        }
        asm volatile("cp.async.commit_group;");
    };

    float acc[4][4][4];
#pragma unroll
    for (int i = 0; i < 4; i++)
#pragma unroll
        for (int j = 0; j < 4; j++)
#pragma unroll
            for (int k = 0; k < 4; k++) acc[i][j][k] = 0.f;

    issue(0, 0);
    asm volatile("cp.async.wait_group 0;");
    __syncthreads();

#pragma unroll 1
    for (int kt = 0; kt < 8; kt++) {
        const int buf = kt & 1;
        if (kt < 7) issue(kt + 1, buf ^ 1);
        bf16* Ah = pl[0] + buf * G0_P;
        bf16* Al = pl[1] + buf * G0_P;
        bf16* Wh = pl[2] + buf * G0_P;
        bf16* Wl = pl[3] + buf * G0_P;
#pragma unroll
        for (int ks = 0; ks < 2; ks++) {
            uint32_t bh[2][4], bl[2][4];
#pragma unroll
            for (int p = 0; p < 2; p++) {
                int row = wn * 32 + p * 16 + ((lane >> 4) << 3) + (lane & 7);
                int kk = ks * 16 + ((lane >> 3) & 1) * 8;
                ldsm4(bh[p][0], bh[p][1], bh[p][2], bh[p][3], sptr(&Wh[row * 40 + kk]));
                ldsm4(bl[p][0], bl[p][1], bl[p][2], bl[p][3], sptr(&Wl[row * 40 + kk]));
            }
#pragma unroll
            for (int mt = 0; mt < 4; mt++) {
                int row = wmi * 64 + mt * 16 + (lane & 15);
                int kk = ks * 16 + (lane >> 4) * 8;
                uint32_t ah[4], al[4];
                ldsm4(ah[0], ah[1], ah[2], ah[3], sptr(&Ah[row * 40 + kk]));
                ldsm4(al[0], al[1], al[2], al[3], sptr(&Al[row * 40 + kk]));
#pragma unroll
                for (int nt = 0; nt < 4; nt++) {
                    int p = nt >> 1, q = (nt & 1) * 2;
                    mma16816(acc[mt][nt], ah, bh[p][q], bh[p][q + 1]);
                    mma16816(acc[mt][nt], ah, bl[p][q], bl[p][q + 1]);
                    mma16816(acc[mt][nt], al, bh[p][q], bh[p][q + 1]);
                }
            }
        }
        asm volatile("cp.async.wait_group 0;");
        __syncthreads();
    }

#pragma unroll
    for (int mt = 0; mt < 4; mt++) {
#pragma unroll
        for (int nt = 0; nt < 4; nt++) {
            int col = cb + wn * 32 + nt * 8 + 2 * (lane & 3);
            int r0 = rb + wmi * 64 + mt * 16 + (lane >> 2);
            float b0 = bias[col], b1 = bias[col + 1];
            float v0 = (acc[mt][nt][0] + b0) * SCALE;
            float v1 = (acc[mt][nt][1] + b1) * SCALE;
            float v2 = (acc[mt][nt][2] + b0) * SCALE;
            float v3 = (acc[mt][nt][3] + b1) * SCALE;
            int h = col >> 5, d = col & 31;
            {
                int b = r0 >> 12, s = (r0 >> 3) & 511, vv = r0 & 7;
                int dst = (((h << 3) + vv) * 4 + b) * (SEG * DQ) + s * DQ + d;
                uint32_t hh, ll;
                split2(v0, v1, hh, ll);
                *(uint32_t*)&g_qhi[dst] = hh;
                *(uint32_t*)&g_qlo[dst] = ll;
            }
            {
                int r1 = r0 + 8;
                int b = r1 >> 12, s = (r1 >> 3) & 511, vv = r1 & 7;
                int dst = (((h << 3) + vv) * 4 + b) * (SEG * DQ) + s * DQ + d;
                uint32_t hh, ll;
                split2(v2, v3, hh, ll);
                *(uint32_t*)&g_qhi[dst] = hh;
                *(uint32_t*)&g_qlo[dst] = ll;
            }
        }
    }
}

// ---------------------------------------------------------------------------
// gemm1: fc + bias + residual + fused LN. Tile 128 rows x 256 cols (FULL row
// per CTA -> complete LN statistics), 512 thr (16 warps, 2x8), BK=32,
// 2-stage cp.async of 4 pre-split planes.
// ---------------------------------------------------------------------------
#define G1_A (128 * 40)
#define G1_W (256 * 40)
#define G1_SMEM ((2 * 2 * G1_A + 2 * 2 * G1_W) * 2)   // 122880

__global__ __launch_bounds__(512, 1) void gemm1(
    const bf16* __restrict__ Ah_g, const bf16* __restrict__ Al_g,
    const bf16* __restrict__ Wh_g, const bf16* __restrict__ Wl_g,
    const float* __restrict__ bias, const float* __restrict__ resid,
    const float* __restrict__ gamma, const float* __restrict__ beta,
    float* __restrict__ Cp)
{
    extern __shared__ char smem_raw[];
    bf16* Ahp = (bf16*)smem_raw;        // [2][128][40]
    bf16* Alp = Ahp + 2 * G1_A;
    bf16* Whp = Alp + 2 * G1_A;         // [2][256][40]
    bf16* Wlp = Whp + 2 * G1_W;

    const int rb = blockIdx.x * 128;
    const int tid = threadIdx.x, lane = tid & 31, w = tid >> 5;
    const int wmi = w & 1, wn = w >> 1;   // 2 x 8

    auto issue = [&](int kt, int buf) {
        // A planes: 1024 chunks, W planes: 2048 chunks; 3072 total / 512 thr
#pragma unroll
        for (int u = 0; u < 2; u++) {
            int idx = tid + u * 512;           // 0..1023  A
            int plane = idx >> 9, rem = idx & 511;
            int row = rem >> 2, q = (rem & 3) * 8;
            const bf16* srcp = (plane ? Al_g : Ah_g) + (size_t)(rb + row) * 256 + kt * 32 + q;
            bf16* dstp = (plane ? Alp : Ahp) + buf * G1_A + row * 40 + q;
            cpasync16(sptr(dstp), srcp);
        }
#pragma unroll
        for (int u = 0; u < 4; u++) {
            int idx = tid + u * 512;           // 0..2047  W
            int plane = idx >> 10, rem = idx & 1023;
            int row = rem >> 2, q = (rem & 3) * 8;
            const bf16* srcp = (plane ? Wl_g : Wh_g) + (size_t)row * 256 + kt * 32 + q;
            bf16* dstp = (plane ? Wlp : Whp) + buf * G1_W + row * 40 + q;
            cpasync16(sptr(dstp), srcp);
        }
        asm volatile("cp.async.commit_group;");
    };

    float acc[4][4][4];
#pragma unroll
    for (int i = 0; i < 4; i++)
#pragma unroll
        for (int j = 0; j < 4; j++)
#pragma unroll
            for (int k = 0; k < 4; k++) acc[i][j][k] = 0.f;

    issue(0, 0);
    asm volatile("cp.async.wait_group 0;");
    __syncthreads();

#pragma unroll 1
    for (int kt = 0; kt < 8; kt++) {
        const int buf = kt & 1;
        if (kt < 7) issue(kt + 1, buf ^ 1);
        bf16* Ah = Ahp + buf * G1_A;
        bf16* Al = Alp + buf * G1_A;
        bf16* Wh = Whp + buf * G1_W;
        bf16* Wl = Wlp + buf * G1_W;
#pragma unroll
        for (int ks = 0; ks < 2; ks++) {
            uint32_t bh[2][4], bl[2][4];
#pragma unroll
            for (int p = 0; p < 2; p++) {
                int row = wn * 32 + p * 16 + ((lane >> 4) << 3) + (lane & 7);
                int kk = ks * 16 + ((lane >> 3) & 1) * 8;
                ldsm4(bh[p][0], bh[p][1], bh[p][2], bh[p][3], sptr(&Wh[row * 40 + kk]));
                ldsm4(bl[p][0], bl[p][1], bl[p][2], bl[p][3], sptr(&Wl[row * 40 + kk]));
            }
#pragma unroll
            for (int mt = 0; mt < 4; mt++) {
                int row = wmi * 64 + mt * 16 + (lane & 15);
                int kk = ks * 16 + (lane >> 4) * 8;
                uint32_t ah[4], al[4];
                ldsm4(ah[0], ah[1], ah[2], ah[3], sptr(&Ah[row * 40 + kk]));
                ldsm4(al[0], al[1], al[2], al[3], sptr(&Al[row * 40 + kk]));
#pragma unroll
                for (int nt = 0; nt < 4; nt++) {
                    int p = nt >> 1, q = (nt & 1) * 2;
                    mma16816(acc[mt][nt], ah, bh[p][q], bh[p][q + 1]);
                    mma16816(acc[mt][nt], ah, bl[p][q], bl[p][q + 1]);
                    mma16816(acc[mt][nt], al, bh[p][q], bh[p][q + 1]);
                }
            }
        }
        asm volatile("cp.async.wait_group 0;");
        __syncthreads();
    }

    // bias + residual + fused LayerNorm over full 256-wide rows
    float2* red = (float2*)smem_raw;                  // [128][8]
    float* mus = (float*)(smem_raw + 8192);           // [128]
    float* rss = (float*)(smem_raw + 8192 + 512);     // [128]

#pragma unroll
    for (int mt = 0; mt < 4; mt++) {
        float s0 = 0.f, q0 = 0.f, s1 = 0.f, q1 = 0.f;
        int rl = wmi * 64 + mt * 16 + (lane >> 2);
#pragma unroll
        for (int nt = 0; nt < 4; nt++) {
            int col = wn * 32 + nt * 8 + 2 * (lane & 3);
            float b0 = bias[col], b1 = bias[col + 1];
            float2 rx0 = *(const float2*)&resid[(size_t)(rb + rl) * 256 + col];
            float2 rx1 = *(const float2*)&resid[(size_t)(rb + rl + 8) * 256 + col];
            acc[mt][nt][0] += b0 + rx0.x;
            acc[mt][nt][1] += b1 + rx0.y;
            acc[mt][nt][2] += b0 + rx1.x;
            acc[mt][nt][3] += b1 + rx1.y;
            s0 += acc[mt][nt][0] + acc[mt][nt][1];
            q0 += acc[mt][nt][0] * acc[mt][nt][0] + acc[mt][nt][1] * acc[mt][nt][1];
            s1 += acc[mt][nt][2] + acc[mt][nt][3];
            q1 += acc[mt][nt][2] * acc[mt][nt][2] + acc[mt][nt][3] * acc[mt][nt][3];
        }
#pragma unroll
        for (int o = 1; o <= 2; o <<= 1) {
            s0 += __shfl_xor_sync(0xffffffffu, s0, o);
            q0 += __shfl_xor_sync(0xffffffffu, q0, o);
            s1 += __shfl_xor_sync(0xffffffffu, s1, o);
            q1 += __shfl_xor_sync(0xffffffffu, q1, o);
        }
        if ((lane & 3) == 0) {
            red[rl * 8 + wn] = make_float2(s0, q0);
            red[(rl + 8) * 8 + wn] = make_float2(s1, q1);
        }
    }
    __syncthreads();
    if (tid < 128) {
        float s = 0.f, q = 0.f;
#pragma unroll
        for (int j = 0; j < 8; j++) {
            float2 p = red[tid * 8 + j];
            s += p.x;
            q += p.y;
        }
        float mu = s * (1.f / 256.f);
        float var = q * (1.f / 256.f) - mu * mu;
        mus[tid] = mu;
        rss[tid] = rsqrtf(var + 1e-5f);
    }
    __syncthreads();
#pragma unroll
    for (int nt = 0; nt < 4; nt++) {
        int col = wn * 32 + nt * 8 + 2 * (lane & 3);
        float g0 = gamma[col], g1 = gamma[col + 1];
        float be0 = beta[col], be1 = beta[col + 1];
#pragma unroll
        for (int mt = 0; mt < 4; mt++) {
            int rl = wmi * 64 + mt * 16 + (lane >> 2);
            float mu0 = mus[rl], rs0 = rss[rl];
            float mu1 = mus[rl + 8], rs1 = rss[rl + 8];
            float2 o0 = { (acc[mt][nt][0] - mu0) * rs0 * g0 + be0,
                          (acc[mt][nt][1] - mu0) * rs0 * g1 + be1 };
            float2 o1 = { (acc[mt][nt][2] - mu1) * rs1 * g0 + be0,
                          (acc[mt][nt][3] - mu1) * rs1 * g1 + be1 };
            *(float2*)&Cp[(size_t)(rb + rl) * 256 + col] = o0;
            *(float2*)&Cp[(size_t)(rb + rl + 8) * 256 + col] = o1;
        }
    }
}

// ---------------------------------------------------------------------------
// Attention: 2 CTAs per group (256 query rows each), 256 threads (8 warps).
// Q prescaled. Pipelined softmax(ct)/MMA1(ct+1)/MMA2(ct).
// MMA1: 3 terms. MMA2: 1 term (P_hi x z_hi). Output -> hi/lo planes.
// ---------------------------------------------------------------------------
struct AttnCtx {
    bf16 *zh, *zl;
    int lane;
    uint32_t qfh[2][2][4], qfl[2][2][4];
};

__device__ __forceinline__ void attn_mma1(AttnCtx& c, int ct, float s[2][2][4]) {
#pragma unroll
    for (int i = 0; i < 2; i++)
#pragma unroll
        for (int j = 0; j < 2; j++)
#pragma unroll
            for (int k = 0; k < 4; k++) s[i][j][k] = 0.f;
    const int t0 = ct * 16;
#pragma unroll
    for (int ks = 0; ks < 2; ks++) {
        int zr = t0 + ((c.lane >> 4) << 3) + (c.lane & 7);
        int zk = ks * 16 + ((c.lane >> 3) & 1) * 8;
        uint32_t zbh[4], zbl[4];
        ldsm4(zbh[0], zbh[1], zbh[2], zbh[3], sptr(&c.zh[zr * 40 + zk]));
        ldsm4(zbl[0], zbl[1], zbl[2], zbl[3], sptr(&c.zl[zr * 40 + zk]));
#pragma unroll
        for (int mt = 0; mt < 2; mt++)
#pragma unroll
            for (int nt = 0; nt < 2; nt++) {
                mma16816(s[mt][nt], c.qfh[mt][ks], zbh[nt * 2], zbh[nt * 2 + 1]);
                mma16816(s[mt][nt], c.qfh[mt][ks], zbl[nt * 2], zbl[nt * 2 + 1]);
                mma16816(s[mt][nt], c.qfl[mt][ks], zbh[nt * 2], zbh[nt * 2 + 1]);
            }
    }
}

__device__ __forceinline__ void attn_softmax(float s[2][2][4], uint32_t pah[2][4],
                                             float dn[2][2]) {
#pragma unroll
    for (int mt = 0; mt < 2; mt++)
#pragma unroll
        for (int nt = 0; nt < 2; nt++) {
            float p0 = ex2f(s[mt][nt][0]);
            float p1 = ex2f(s[mt][nt][1]);
            float p2 = ex2f(s[mt][nt][2]);
            float p3 = ex2f(s[mt][nt][3]);
            dn[mt][0] += p0 + p1;
            dn[mt][1] += p2 + p3;
            pah[mt][nt * 2] = pack_bf16(p0, p1);
            pah[mt][nt * 2 + 1] = pack_bf16(p2, p3);
        }
}

__device__ __forceinline__ void attn_mma2(AttnCtx& c, int ct, uint32_t pah[2][4],
                                          float o[2][4][4]) {
    const int t0 = ct * 16;
#pragma unroll
    for (int dp = 0; dp < 2; dp++) {
        int zr = t0 + (((c.lane >> 3) & 1) << 3) + (c.lane & 7);
        int zc = dp * 16 + (c.lane >> 4) * 8;
        uint32_t zth[4];
        ldsm4t(zth[0], zth[1], zth[2], zth[3], sptr(&c.zh[zr * 40 + zc]));
#pragma unroll
        for (int mt = 0; mt < 2; mt++)
#pragma unroll
            for (int nt = 0; nt < 2; nt++) {
                mma16816(o[mt][dp * 2 + nt], pah[mt], zth[nt * 2], zth[nt * 2 + 1]);
            }
    }
}

__global__ __launch_bounds__(256, 2) void attn_mma() {
    extern __shared__ __align__(16) bf16 zsm[];
    AttnCtx c;
    c.zh = zsm;
    c.zl = zsm + 512 * 40;

    const int g = blockIdx.x >> 1, half = blockIdx.x & 1;
    const int tid = threadIdx.x, w = tid >> 5;
    c.lane = tid & 31;
    const int lane = c.lane;
    const int h = g >> 5, v = (g >> 2) & 7, b = g & 3;

    const bf16* zph = g_zhi + (size_t)g * SEG * DQ;
    const bf16* zpl = g_zlo + (size_t)g * SEG * DQ;
#pragma unroll
    for (int u = 0; u < 8; u++) {
        int idx = tid + u * 256;
        int row = idx >> 2, qq = idx & 3;
        *(uint4*)&c.zh[row * 40 + qq * 8] = *(const uint4*)&zph[row * 32 + qq * 8];
        *(uint4*)&c.zl[row * 40 + qq * 8] = *(const uint4*)&zpl[row * 32 + qq * 8];
    }

    const bf16* qph = g_qhi + (size_t)g * SEG * DQ;
    const bf16* qpl = g_qlo + (size_t)g * SEG * DQ;
    const int m0 = half * 256 + w * 32;
#pragma unroll
    for (int mt = 0; mt < 2; mt++)
#pragma unroll
        for (int ks = 0; ks < 2; ks++) {
            int row = m0 + mt * 16 + (lane >> 2);
            int kk = ks * 16 + 2 * (lane & 3);
            c.qfh[mt][ks][0] = *(const uint32_t*)&qph[row * 32 + kk];
            c.qfh[mt][ks][1] = *(const uint32_t*)&qph[(row + 8) * 32 + kk];
            c.qfh[mt][ks][2] = *(const uint32_t*)&qph[row * 32 + kk + 8];
            c.qfh[mt][ks][3] = *(const uint32_t*)&qph[(row + 8) * 32 + kk + 8];
            c.qfl[mt][ks][0] = *(const uint32_t*)&qpl[row * 32 + kk];
            c.qfl[mt][ks][1] = *(const uint32_t*)&qpl[(row + 8) * 32 + kk];
            c.qfl[mt][ks][2] = *(const uint32_t*)&qpl[row * 32 + kk + 8];
            c.qfl[mt][ks][3] = *(const uint32_t*)&qpl[(row + 8) * 32 + kk + 8];
        }

    float o[2][4][4];
#pragma unroll
    for (int i = 0; i < 2; i++)
#pragma unroll
        for (int j = 0; j < 4; j++)
#pragma unroll
            for (int k = 0; k < 4; k++) o[i][j][k] = 0.f;
    float dn[2][2] = {{0.f, 0.f}, {0.f, 0.f}};

    __syncthreads();

    float s[2][2][4];
    attn_mma1(c, 0, s);

#pragma unroll 1
    for (int ct = 0; ct < 31; ct++) {
        uint32_t pah[2][4];
        attn_softmax(s, pah, dn);
        float s2[2][2][4];
        attn_mma1(c, ct + 1, s2);
        attn_mma2(c, ct, pah, o);
#pragma unroll
        for (int i = 0; i < 2; i++)
#pragma unroll
            for (int j = 0; j < 2; j++)
#pragma unroll
                for (int k = 0; k < 4; k++) s[i][j][k] = s2[i][j][k];
    }
    {
        uint32_t pah[2][4];
        attn_softmax(s, pah, dn);
        attn_mma2(c, 31, pah, o);
    }

    float inv[2][2];
#pragma unroll
    for (int mt = 0; mt < 2; mt++)
#pragma unroll
        for (int rh = 0; rh < 2; rh++) {
            float d = dn[mt][rh];
            d += __shfl_xor_sync(0xffffffffu, d, 1);
            d += __shfl_xor_sync(0xffffffffu, d, 2);
            inv[mt][rh] = __fdividef(1.f, d);
        }

#pragma unroll
    for (int mt = 0; mt < 2; mt++) {
        int s0 = m0 + mt * 16 + (lane >> 2);
        int r0 = ((b * SEG + s0) * 8) + v;
        int r1 = ((b * SEG + s0 + 8) * 8) + v;
#pragma unroll
        for (int n = 0; n < 4; n++) {
            int col = h * 32 + n * 8 + 2 * (lane & 3);
            uint32_t hh, ll;
            split2(o[mt][n][0] * inv[mt][0], o[mt][n][1] * inv[mt][0], hh, ll);
            *(uint32_t*)&g_ohi[(size_t)r0 * 256 + col] = hh;
            *(uint32_t*)&g_olo[(size_t)r0 * 256 + col] = ll;
            split2(o[mt][n][2] * inv[mt][1], o[mt][n][3] * inv[mt][1], hh, ll);
            *(uint32_t*)&g_ohi[(size_t)r1 * 256 + col] = hh;
            *(uint32_t*)&g_olo[(size_t)r1 * 256 + col] = ll;
        }
    }
}

// ---------------------------------------------------------------------------

extern "C" void kernel_launch(void* const* d_in, const int* in_sizes, int n_in,
                              void* d_out, int out_size)
{
    const float* x     = (const float*)d_in[0];
    const float* z     = (const float*)d_in[1];
    const float* wq    = (const float*)d_in[2];
    const float* wqb   = (const float*)d_in[3];
    const float* fcw   = (const float*)d_in[4];
    const float* fcb   = (const float*)d_in[5];
    const float* gamma = (const float*)d_in[6];
    const float* beta  = (const float*)d_in[7];
    float* y = (float*)d_out;

    static bf16 *xh_p = nullptr, *xl_p, *oh_p, *ol_p, *wqh_p, *wql_p, *fh_p, *fl_p;
    if (!xh_p) {
        cudaGetSymbolAddress((void**)&xh_p, g_xhi);
        cudaGetSymbolAddress((void**)&xl_p, g_xlo);
        cudaGetSymbolAddress((void**)&oh_p, g_ohi);
        cudaGetSymbolAddress((void**)&ol_p, g_olo);
        cudaGetSymbolAddress((void**)&wqh_p, g_wqh);
        cudaGetSymbolAddress((void**)&wql_p, g_wql);
        cudaGetSymbolAddress((void**)&fh_p, g_fh);
        cudaGetSymbolAddress((void**)&fl_p, g_fl);
        cudaFuncSetAttribute(gemm0, cudaFuncAttributeMaxDynamicSharedMemorySize, G0_SMEM);
        cudaFuncSetAttribute(gemm1, cudaFuncAttributeMaxDynamicSharedMemorySize, G1_SMEM);
        cudaFuncSetAttribute(attn_mma, cudaFuncAttributeMaxDynamicSharedMemorySize, 2 * 512 * 40 * 2);
    }

    prep<<<8320, 256>>>(z, x, wq, fcw);
    dim3 g0grid(2, 128);
    gemm0<<<g0grid, 256, G0_SMEM>>>(xh_p, xl_p, wqh_p, wql_p, wqb);
    attn_mma<<<NG * 2, 256, 2 * 512 * 40 * 2>>>();
    gemm1<<<128, 512, G1_SMEM>>>(oh_p, ol_p, fh_p, fl_p, fcb, x, gamma, beta, y);
}

// round 7
// speedup vs baseline: 4.3760x; 1.4945x over previous
#include <cuda_runtime.h>
#include <cuda_bf16.h>
#include <cstdint>

// ---------------------------------------------------------------------------
// bs=4 seg=512 nv=8 h=8 dq=32 din=256; tokens=16384, groups=256
// HMMA (mma.sync bf16) everywhere; precision plan from error budget:
//   weights: hi/lo bf16 split (2-term GEMMs: Ah*Wh + Ah*Wl)
//   activations (x, q, z, o): single bf16 hi plane
//  prep  : z,x -> bf16; Wq,fc -> bf16 hi/lo
//  gemm0 : q = (x@WqT + b)*log2e/temp -> per-group q plane (128x128, 2-term)
//  attn  : 2 CTAs/group; MMA1 1-term, ex2 softmax, MMA2 1-term -> o plane
//  gemm1 : fc (2-term) + bias + residual + fused LayerNorm -> d_out
// ---------------------------------------------------------------------------

#define NTOK 16384
#define SEG  512
#define DQ   32
#define NG   256
#define SCALE 0.2550353055731662f   // log2(e)/sqrt(32)

typedef __nv_bfloat16 bf16;

__device__ bf16 g_qh[NG * SEG * DQ];
__device__ bf16 g_zh[NG * SEG * DQ];
__device__ bf16 g_xh[NTOK * 256];
__device__ bf16 g_oh[NTOK * 256];
__device__ bf16 g_wqh[256 * 256];
__device__ bf16 g_wql[256 * 256];
__device__ bf16 g_fh[256 * 256];
__device__ bf16 g_fl[256 * 256];

// ---------------- helpers ----------------
__device__ __forceinline__ uint32_t sptr(const void* p) {
    return (uint32_t)__cvta_generic_to_shared(p);
}
__device__ __forceinline__ void ldsm4(uint32_t& r0, uint32_t& r1, uint32_t& r2,
                                      uint32_t& r3, uint32_t a) {
    asm volatile("ldmatrix.sync.aligned.m8n8.x4.shared.b16 {%0,%1,%2,%3}, [%4];"
                 : "=r"(r0), "=r"(r1), "=r"(r2), "=r"(r3) : "r"(a));
}
__device__ __forceinline__ void ldsm4t(uint32_t& r0, uint32_t& r1, uint32_t& r2,
                                       uint32_t& r3, uint32_t a) {
    asm volatile("ldmatrix.sync.aligned.m8n8.x4.trans.shared.b16 {%0,%1,%2,%3}, [%4];"
                 : "=r"(r0), "=r"(r1), "=r"(r2), "=r"(r3) : "r"(a));
}
__device__ __forceinline__ void mma16816(float* d, const uint32_t* a,
                                         uint32_t b0, uint32_t b1) {
    asm volatile(
        "mma.sync.aligned.m16n8k16.row.col.f32.bf16.bf16.f32 "
        "{%0,%1,%2,%3}, {%4,%5,%6,%7}, {%8,%9}, {%0,%1,%2,%3};"
        : "+f"(d[0]), "+f"(d[1]), "+f"(d[2]), "+f"(d[3])
        : "r"(a[0]), "r"(a[1]), "r"(a[2]), "r"(a[3]), "r"(b0), "r"(b1));
}
__device__ __forceinline__ void split2(float x, float y, uint32_t& hi, uint32_t& lo) {
    __nv_bfloat162 h = __floats2bfloat162_rn(x, y);
    float hx = __bfloat162float(h.x), hy = __bfloat162float(h.y);
    __nv_bfloat162 l = __floats2bfloat162_rn(x - hx, y - hy);
    hi = *(uint32_t*)&h;
    lo = *(uint32_t*)&l;
}
__device__ __forceinline__ uint32_t pack_bf16(float x, float y) {
    __nv_bfloat162 h = __floats2bfloat162_rn(x, y);
    return *(uint32_t*)&h;
}
__device__ __forceinline__ float ex2f(float x) {
    float r;
    asm("ex2.approx.f32 %0, %1;" : "=f"(r) : "f"(x));
    return r;
}
__device__ __forceinline__ void cpasync16(uint32_t dst, const void* src) {
    asm volatile("cp.async.ca.shared.global [%0], [%1], 16;" :: "r"(dst), "l"(src));
}

// ---------------- prep ----------------
// z,x -> single bf16 plane; wq,fcw -> hi/lo planes.
__global__ __launch_bounds__(256) void prep(const float* __restrict__ z,
                                            const float* __restrict__ x,
                                            const float* __restrict__ wq,
                                            const float* __restrict__ fcw) {
    int blk = blockIdx.x;
    int tidx = threadIdx.x;
    if (blk < 8192) {  // activations: bf16 only
        const float* src = (blk < 4096) ? z : x;
        bf16* dh = (blk < 4096) ? g_zh : g_xh;
        int i = ((blk < 4096) ? blk : blk - 4096) * 256 + tidx;
        float4 v = ((const float4*)src)[i];
        uint32_t h0 = pack_bf16(v.x, v.y);
        uint32_t h1 = pack_bf16(v.z, v.w);
        ((uint2*)dh)[i] = make_uint2(h0, h1);
    } else {           // weights: hi/lo split
        const float* src = (blk < 8256) ? wq : fcw;
        bf16* dh = (blk < 8256) ? g_wqh : g_fh;
        bf16* dl = (blk < 8256) ? g_wql : g_fl;
        int i = ((blk < 8256) ? blk - 8192 : blk - 8256) * 256 + tidx;
        float4 v = ((const float4*)src)[i];
        uint32_t h0, l0, h1, l1;
        split2(v.x, v.y, h0, l0);
        split2(v.z, v.w, h1, l1);
        ((uint2*)dh)[i] = make_uint2(h0, h1);
        ((uint2*)dl)[i] = make_uint2(l0, l1);
    }
}

// ---------------------------------------------------------------------------
// gemm0: q-projection, 2-term (xh*Wh + xh*Wl). 128x128 tile, 256 thr
// (8 warps 2x4, warp 64x32), BK=32, 2-stage cp.async, 3 smem planes.
// out = (acc + bias) * SCALE -> q plane, per-group layout.
// ---------------------------------------------------------------------------
#define G0_P (128 * 40)                 // bf16 elems per plane per stage
#define G0_SMEM (2 * 3 * G0_P * 2)      // 61440

__global__ __launch_bounds__(256, 2) void gemm0(
    const bf16* __restrict__ Ah_g,
    const bf16* __restrict__ Wh_g, const bf16* __restrict__ Wl_g,
    const float* __restrict__ bias)
{
    extern __shared__ char smem_raw[];
    bf16* pl[3];
    pl[0] = (bf16*)smem_raw;          // Ah [2][128][40]
    pl[1] = pl[0] + 2 * G0_P;         // Wh
    pl[2] = pl[1] + 2 * G0_P;         // Wl

    const int rb = blockIdx.y * 128, cb = blockIdx.x * 128;
    const int tid = threadIdx.x, lane = tid & 31, w = tid >> 5;
    const int wmi = w & 1, wn = w >> 1;

    const bf16* gsrc[3] = { Ah_g, Wh_g, Wl_g };
    const int gbase[3] = { rb, cb, cb };

    auto issue = [&](int kt, int buf) {
#pragma unroll
        for (int u = 0; u < 6; u++) {
            int idx = tid + u * 256;          // 1536 16B chunks
            int plane = idx >> 9, rem = idx & 511;
            int row = rem >> 2, q = (rem & 3) * 8;
            const bf16* srcp = gsrc[plane] + (size_t)(gbase[plane] + row) * 256 + kt * 32 + q;
            cpasync16(sptr(pl[plane] + buf * G0_P + row * 40 + q), srcp);
        }
        asm volatile("cp.async.commit_group;");
    };

    float acc[4][4][4];
#pragma unroll
    for (int i = 0; i < 4; i++)
#pragma unroll
        for (int j = 0; j < 4; j++)
#pragma unroll
            for (int k = 0; k < 4; k++) acc[i][j][k] = 0.f;

    issue(0, 0);
    asm volatile("cp.async.wait_group 0;");
    __syncthreads();

#pragma unroll 1
    for (int kt = 0; kt < 8; kt++) {
        const int buf = kt & 1;
        if (kt < 7) issue(kt + 1, buf ^ 1);
        bf16* Ah = pl[0] + buf * G0_P;
        bf16* Wh = pl[1] + buf * G0_P;
        bf16* Wl = pl[2] + buf * G0_P;
#pragma unroll
        for (int ks = 0; ks < 2; ks++) {
            uint32_t bh[2][4], bl[2][4];
#pragma unroll
            for (int p = 0; p < 2; p++) {
                int row = wn * 32 + p * 16 + ((lane >> 4) << 3) + (lane & 7);
                int kk = ks * 16 + ((lane >> 3) & 1) * 8;
                ldsm4(bh[p][0], bh[p][1], bh[p][2], bh[p][3], sptr(&Wh[row * 40 + kk]));
                ldsm4(bl[p][0], bl[p][1], bl[p][2], bl[p][3], sptr(&Wl[row * 40 + kk]));
            }
#pragma unroll
            for (int mt = 0; mt < 4; mt++) {
                int row = wmi * 64 + mt * 16 + (lane & 15);
                int kk = ks * 16 + (lane >> 4) * 8;
                uint32_t ah[4];
                ldsm4(ah[0], ah[1], ah[2], ah[3], sptr(&Ah[row * 40 + kk]));
#pragma unroll
                for (int nt = 0; nt < 4; nt++) {
                    int p = nt >> 1, q = (nt & 1) * 2;
                    mma16816(acc[mt][nt], ah, bh[p][q], bh[p][q + 1]);
                    mma16816(acc[mt][nt], ah, bl[p][q], bl[p][q + 1]);
                }
            }
        }
        asm volatile("cp.async.wait_group 0;");
        __syncthreads();
    }

#pragma unroll
    for (int mt = 0; mt < 4; mt++) {
#pragma unroll
        for (int nt = 0; nt < 4; nt++) {
            int col = cb + wn * 32 + nt * 8 + 2 * (lane & 3);
            int r0 = rb + wmi * 64 + mt * 16 + (lane >> 2);
            float b0 = bias[col], b1 = bias[col + 1];
            float v0 = (acc[mt][nt][0] + b0) * SCALE;
            float v1 = (acc[mt][nt][1] + b1) * SCALE;
            float v2 = (acc[mt][nt][2] + b0) * SCALE;
            float v3 = (acc[mt][nt][3] + b1) * SCALE;
            int h = col >> 5, d = col & 31;
            {
                int b = r0 >> 12, s = (r0 >> 3) & 511, vv = r0 & 7;
                int dst = (((h << 3) + vv) * 4 + b) * (SEG * DQ) + s * DQ + d;
                *(uint32_t*)&g_qh[dst] = pack_bf16(v0, v1);
            }
            {
                int r1 = r0 + 8;
                int b = r1 >> 12, s = (r1 >> 3) & 511, vv = r1 & 7;
                int dst = (((h << 3) + vv) * 4 + b) * (SEG * DQ) + s * DQ + d;
                *(uint32_t*)&g_qh[dst] = pack_bf16(v2, v3);
            }
        }
    }
}

// ---------------------------------------------------------------------------
// gemm1: fc (2-term: oh*Fh + oh*Fl) + bias + residual + fused LN.
// Tile 128 rows x 256 cols (full row -> complete LN stats), 512 thr (2x8
// warps), BK=32, 2-stage cp.async, 3 smem planes.
// ---------------------------------------------------------------------------
#define G1_A (128 * 40)
#define G1_W (256 * 40)
#define G1_SMEM ((2 * G1_A + 2 * 2 * G1_W) * 2)   // 102400

__global__ __launch_bounds__(512, 1) void gemm1(
    const bf16* __restrict__ Ah_g,
    const bf16* __restrict__ Wh_g, const bf16* __restrict__ Wl_g,
    const float* __restrict__ bias, const float* __restrict__ resid,
    const float* __restrict__ gamma, const float* __restrict__ beta,
    float* __restrict__ Cp)
{
    extern __shared__ char smem_raw[];
    bf16* Ahp = (bf16*)smem_raw;        // [2][128][40]
    bf16* Whp = Ahp + 2 * G1_A;         // [2][256][40]
    bf16* Wlp = Whp + 2 * G1_W;

    const int rb = blockIdx.x * 128;
    const int tid = threadIdx.x, lane = tid & 31, w = tid >> 5;
    const int wmi = w & 1, wn = w >> 1;   // 2 x 8

    auto issue = [&](int kt, int buf) {
        {   // A: 512 chunks
            int idx = tid;
            if (idx < 512) {
                int row = idx >> 2, q = (idx & 3) * 8;
                cpasync16(sptr(Ahp + buf * G1_A + row * 40 + q),
                          Ah_g + (size_t)(rb + row) * 256 + kt * 32 + q);
            }
        }
#pragma unroll
        for (int u = 0; u < 4; u++) {      // W: 2048 chunks
            int idx = tid + u * 512;
            int plane = idx >> 10, rem = idx & 1023;
            int row = rem >> 2, q = (rem & 3) * 8;
            const bf16* srcp = (plane ? Wl_g : Wh_g) + (size_t)row * 256 + kt * 32 + q;
            bf16* dstp = (plane ? Wlp : Whp) + buf * G1_W + row * 40 + q;
            cpasync16(sptr(dstp), srcp);
        }
        asm volatile("cp.async.commit_group;");
    };

    float acc[4][4][4];
#pragma unroll
    for (int i = 0; i < 4; i++)
#pragma unroll
        for (int j = 0; j < 4; j++)
#pragma unroll
            for (int k = 0; k < 4; k++) acc[i][j][k] = 0.f;

    issue(0, 0);
    asm volatile("cp.async.wait_group 0;");
    __syncthreads();

#pragma unroll 1
    for (int kt = 0; kt < 8; kt++) {
        const int buf = kt & 1;
        if (kt < 7) issue(kt + 1, buf ^ 1);
        bf16* Ah = Ahp + buf * G1_A;
        bf16* Wh = Whp + buf * G1_W;
        bf16* Wl = Wlp + buf * G1_W;
#pragma unroll
        for (int ks = 0; ks < 2; ks++) {
            uint32_t bh[2][4], bl[2][4];
#pragma unroll
            for (int p = 0; p < 2; p++) {
                int row = wn * 32 + p * 16 + ((lane >> 4) << 3) + (lane & 7);
                int kk = ks * 16 + ((lane >> 3) & 1) * 8;
                ldsm4(bh[p][0], bh[p][1], bh[p][2], bh[p][3], sptr(&Wh[row * 40 + kk]));
                ldsm4(bl[p][0], bl[p][1], bl[p][2], bl[p][3], sptr(&Wl[row * 40 + kk]));
            }
#pragma unroll
            for (int mt = 0; mt < 4; mt++) {
                int row = wmi * 64 + mt * 16 + (lane & 15);
                int kk = ks * 16 + (lane >> 4) * 8;
                uint32_t ah[4];
                ldsm4(ah[0], ah[1], ah[2], ah[3], sptr(&Ah[row * 40 + kk]));
#pragma unroll
                for (int nt = 0; nt < 4; nt++) {
                    int p = nt >> 1, q = (nt & 1) * 2;
                    mma16816(acc[mt][nt], ah, bh[p][q], bh[p][q + 1]);
                    mma16816(acc[mt][nt], ah, bl[p][q], bl[p][q + 1]);
                }
            }
        }
        asm volatile("cp.async.wait_group 0;");
        __syncthreads();
    }

    // bias + residual + fused LayerNorm over full 256-wide rows
    float2* red = (float2*)smem_raw;                  // [128][8]
    float* mus = (float*)(smem_raw + 8192);           // [128]
    float* rss = (float*)(smem_raw + 8192 + 512);     // [128]

#pragma unroll
    for (int mt = 0; mt < 4; mt++) {
        float s0 = 0.f, q0 = 0.f, s1 = 0.f, q1 = 0.f;
        int rl = wmi * 64 + mt * 16 + (lane >> 2);
#pragma unroll
        for (int nt = 0; nt < 4; nt++) {
            int col = wn * 32 + nt * 8 + 2 * (lane & 3);
            float b0 = bias[col], b1 = bias[col + 1];
            float2 rx0 = *(const float2*)&resid[(size_t)(rb + rl) * 256 + col];
            float2 rx1 = *(const float2*)&resid[(size_t)(rb + rl + 8) * 256 + col];
            acc[mt][nt][0] += b0 + rx0.x;
            acc[mt][nt][1] += b1 + rx0.y;
            acc[mt][nt][2] += b0 + rx1.x;
            acc[mt][nt][3] += b1 + rx1.y;
            s0 += acc[mt][nt][0] + acc[mt][nt][1];
            q0 += acc[mt][nt][0] * acc[mt][nt][0] + acc[mt][nt][1] * acc[mt][nt][1];
            s1 += acc[mt][nt][2] + acc[mt][nt][3];
            q1 += acc[mt][nt][2] * acc[mt][nt][2] + acc[mt][nt][3] * acc[mt][nt][3];
        }
#pragma unroll
        for (int o = 1; o <= 2; o <<= 1) {
            s0 += __shfl_xor_sync(0xffffffffu, s0, o);
            q0 += __shfl_xor_sync(0xffffffffu, q0, o);
            s1 += __shfl_xor_sync(0xffffffffu, s1, o);
            q1 += __shfl_xor_sync(0xffffffffu, q1, o);
        }
        if ((lane & 3) == 0) {
            red[rl * 8 + wn] = make_float2(s0, q0);
            red[(rl + 8) * 8 + wn] = make_float2(s1, q1);
        }
    }
    __syncthreads();
    if (tid < 128) {
        float s = 0.f, q = 0.f;
#pragma unroll
        for (int j = 0; j < 8; j++) {
            float2 p = red[tid * 8 + j];
            s += p.x;
            q += p.y;
        }
        float mu = s * (1.f / 256.f);
        float var = q * (1.f / 256.f) - mu * mu;
        mus[tid] = mu;
        rss[tid] = rsqrtf(var + 1e-5f);
    }
    __syncthreads();
#pragma unroll
    for (int nt = 0; nt < 4; nt++) {
        int col = wn * 32 + nt * 8 + 2 * (lane & 3);
        float g0 = gamma[col], g1 = gamma[col + 1];
        float be0 = beta[col], be1 = beta[col + 1];
#pragma unroll
        for (int mt = 0; mt < 4; mt++) {
            int rl = wmi * 64 + mt * 16 + (lane >> 2);
            float mu0 = mus[rl], rs0 = rss[rl];
            float mu1 = mus[rl + 8], rs1 = rss[rl + 8];
            float2 o0 = { (acc[mt][nt][0] - mu0) * rs0 * g0 + be0,
                          (acc[mt][nt][1] - mu0) * rs0 * g1 + be1 };
            float2 o1 = { (acc[mt][nt][2] - mu1) * rs1 * g0 + be0,
                          (acc[mt][nt][3] - mu1) * rs1 * g1 + be1 };
            *(float2*)&Cp[(size_t)(rb + rl) * 256 + col] = o0;
            *(float2*)&Cp[(size_t)(rb + rl + 8) * 256 + col] = o1;
        }
    }
}

// ---------------------------------------------------------------------------
// Attention: 2 CTAs/group (256 query rows), 256 thr (8 warps x 32 rows).
// z bf16-only in smem (40KB). MMA1 1-term (qh x zh), ex2, MMA2 1-term.
// Pipelined softmax(ct)/MMA1(ct+1)/MMA2(ct). Output -> o plane.
// ---------------------------------------------------------------------------
struct AttnCtx {
    bf16* zh;
    int lane;
    uint32_t qfh[2][2][4];
};

__device__ __forceinline__ void attn_mma1(AttnCtx& c, int ct, float s[2][2][4]) {
#pragma unroll
    for (int i = 0; i < 2; i++)
#pragma unroll
        for (int j = 0; j < 2; j++)
#pragma unroll
            for (int k = 0; k < 4; k++) s[i][j][k] = 0.f;
    const int t0 = ct * 16;
#pragma unroll
    for (int ks = 0; ks < 2; ks++) {
        int zr = t0 + ((c.lane >> 4) << 3) + (c.lane & 7);
        int zk = ks * 16 + ((c.lane >> 3) & 1) * 8;
        uint32_t zbh[4];
        ldsm4(zbh[0], zbh[1], zbh[2], zbh[3], sptr(&c.zh[zr * 40 + zk]));
#pragma unroll
        for (int mt = 0; mt < 2; mt++)
#pragma unroll
            for (int nt = 0; nt < 2; nt++)
                mma16816(s[mt][nt], c.qfh[mt][ks], zbh[nt * 2], zbh[nt * 2 + 1]);
    }
}

__device__ __forceinline__ void attn_softmax(float s[2][2][4], uint32_t pah[2][4],
                                             float dn[2][2]) {
#pragma unroll
    for (int mt = 0; mt < 2; mt++)
#pragma unroll
        for (int nt = 0; nt < 2; nt++) {
            float p0 = ex2f(s[mt][nt][0]);
            float p1 = ex2f(s[mt][nt][1]);
            float p2 = ex2f(s[mt][nt][2]);
            float p3 = ex2f(s[mt][nt][3]);
            dn[mt][0] += p0 + p1;
            dn[mt][1] += p2 + p3;
            pah[mt][nt * 2] = pack_bf16(p0, p1);
            pah[mt][nt * 2 + 1] = pack_bf16(p2, p3);
        }
}

__device__ __forceinline__ void attn_mma2(AttnCtx& c, int ct, uint32_t pah[2][4],
                                          float o[2][4][4]) {
    const int t0 = ct * 16;
#pragma unroll
    for (int dp = 0; dp < 2; dp++) {
        int zr = t0 + (((c.lane >> 3) & 1) << 3) + (c.lane & 7);
        int zc = dp * 16 + (c.lane >> 4) * 8;
        uint32_t zth[4];
        ldsm4t(zth[0], zth[1], zth[2], zth[3], sptr(&c.zh[zr * 40 + zc]));
#pragma unroll
        for (int mt = 0; mt < 2; mt++)
#pragma unroll
            for (int nt = 0; nt < 2; nt++)
                mma16816(o[mt][dp * 2 + nt], pah[mt], zth[nt * 2], zth[nt * 2 + 1]);
    }
}

__global__ __launch_bounds__(256, 2) void attn_mma() {
    extern __shared__ __align__(16) bf16 zsm[];
    AttnCtx c;
    c.zh = zsm;   // [512][40]

    const int g = blockIdx.x >> 1, half = blockIdx.x & 1;
    const int tid = threadIdx.x, w = tid >> 5;
    c.lane = tid & 31;
    const int lane = c.lane;
    const int h = g >> 5, v = (g >> 2) & 7, b = g & 3;

    const bf16* zph = g_zh + (size_t)g * SEG * DQ;
#pragma unroll
    for (int u = 0; u < 8; u++) {
        int idx = tid + u * 256;
        int row = idx >> 2, qq = idx & 3;
        *(uint4*)&c.zh[row * 40 + qq * 8] = *(const uint4*)&zph[row * 32 + qq * 8];
    }

    const bf16* qph = g_qh + (size_t)g * SEG * DQ;
    const int m0 = half * 256 + w * 32;
#pragma unroll
    for (int mt = 0; mt < 2; mt++)
#pragma unroll
        for (int ks = 0; ks < 2; ks++) {
            int row = m0 + mt * 16 + (lane >> 2);
            int kk = ks * 16 + 2 * (lane & 3);
            c.qfh[mt][ks][0] = *(const uint32_t*)&qph[row * 32 + kk];
            c.qfh[mt][ks][1] = *(const uint32_t*)&qph[(row + 8) * 32 + kk];
            c.qfh[mt][ks][2] = *(const uint32_t*)&qph[row * 32 + kk + 8];
            c.qfh[mt][ks][3] = *(const uint32_t*)&qph[(row + 8) * 32 + kk + 8];
        }

    float o[2][4][4];
#pragma unroll
    for (int i = 0; i < 2; i++)
#pragma unroll
        for (int j = 0; j < 4; j++)
#pragma unroll
            for (int k = 0; k < 4; k++) o[i][j][k] = 0.f;
    float dn[2][2] = {{0.f, 0.f}, {0.f, 0.f}};

    __syncthreads();

    float s[2][2][4];
    attn_mma1(c, 0, s);

#pragma unroll 1
    for (int ct = 0; ct < 31; ct++) {
        uint32_t pah[2][4];
        attn_softmax(s, pah, dn);
        float s2[2][2][4];
        attn_mma1(c, ct + 1, s2);
        attn_mma2(c, ct, pah, o);
#pragma unroll
        for (int i = 0; i < 2; i++)
#pragma unroll
            for (int j = 0; j < 2; j++)
#pragma unroll
                for (int k = 0; k < 4; k++) s[i][j][k] = s2[i][j][k];
    }
    {
        uint32_t pah[2][4];
        attn_softmax(s, pah, dn);
        attn_mma2(c, 31, pah, o);
    }

    float inv[2][2];
#pragma unroll
    for (int mt = 0; mt < 2; mt++)
#pragma unroll
        for (int rh = 0; rh < 2; rh++) {
            float d = dn[mt][rh];
            d += __shfl_xor_sync(0xffffffffu, d, 1);
            d += __shfl_xor_sync(0xffffffffu, d, 2);
            inv[mt][rh] = __fdividef(1.f, d);
        }

    // store O plane, token-major
#pragma unroll
    for (int mt = 0; mt < 2; mt++) {
        int s0 = m0 + mt * 16 + (lane >> 2);
        int r0 = ((b * SEG + s0) * 8) + v;
        int r1 = ((b * SEG + s0 + 8) * 8) + v;
#pragma unroll
        for (int n = 0; n < 4; n++) {
            int col = h * 32 + n * 8 + 2 * (lane & 3);
            *(uint32_t*)&g_oh[(size_t)r0 * 256 + col] =
                pack_bf16(o[mt][n][0] * inv[mt][0], o[mt][n][1] * inv[mt][0]);
            *(uint32_t*)&g_oh[(size_t)r1 * 256 + col] =
                pack_bf16(o[mt][n][2] * inv[mt][1], o[mt][n][3] * inv[mt][1]);
        }
    }
}

// ---------------------------------------------------------------------------

extern "C" void kernel_launch(void* const* d_in, const int* in_sizes, int n_in,
                              void* d_out, int out_size)
{
    const float* x     = (const float*)d_in[0];
    const float* z     = (const float*)d_in[1];
    const float* wq    = (const float*)d_in[2];
    const float* wqb   = (const float*)d_in[3];
    const float* fcw   = (const float*)d_in[4];
    const float* fcb   = (const float*)d_in[5];
    const float* gamma = (const float*)d_in[6];
    const float* beta  = (const float*)d_in[7];
    float* y = (float*)d_out;

    static bf16 *xh_p = nullptr, *oh_p, *wqh_p, *wql_p, *fh_p, *fl_p;
    if (!xh_p) {
        cudaGetSymbolAddress((void**)&xh_p, g_xh);
        cudaGetSymbolAddress((void**)&oh_p, g_oh);
        cudaGetSymbolAddress((void**)&wqh_p, g_wqh);
        cudaGetSymbolAddress((void**)&wql_p, g_wql);
        cudaGetSymbolAddress((void**)&fh_p, g_fh);
        cudaGetSymbolAddress((void**)&fl_p, g_fl);
        cudaFuncSetAttribute(gemm0, cudaFuncAttributeMaxDynamicSharedMemorySize, G0_SMEM);
        cudaFuncSetAttribute(gemm1, cudaFuncAttributeMaxDynamicSharedMemorySize, G1_SMEM);
        cudaFuncSetAttribute(attn_mma, cudaFuncAttributeMaxDynamicSharedMemorySize, 512 * 40 * 2);
    }

    prep<<<8320, 256>>>(z, x, wq, fcw);
    dim3 g0grid(2, 128);
    gemm0<<<g0grid, 256, G0_SMEM>>>(xh_p, wqh_p, wql_p, wqb);
    attn_mma<<<NG * 2, 256, 512 * 40 * 2>>>();
    gemm1<<<128, 512, G1_SMEM>>>(oh_p, fh_p, fl_p, fcb, x, gamma, beta, y);
}

// round 8
// speedup vs baseline: 5.0319x; 1.1499x over previous
#include <cuda_runtime.h>
#include <cuda_fp16.h>
#include <cstdint>

// ---------------------------------------------------------------------------
// bs=4 seg=512 nv=8 h=8 dq=32 din=256; tokens=16384, groups=256
// ALL-FP16 datapath (unit roundoff 2^-11, 8x better than bf16, same HMMA rate)
//  prep  : x, z, Wq, fc -> fp16 planes (single, no hi/lo)
//  gemm0 : q = (x@WqT + b)*log2e/temp -> per-group q plane (1-term HMMA)
//  attn  : 2 CTAs/group; MMA1, ex2 softmax, MMA2 -> o plane (fp16)
//  gemm1 : fc (1-term) + bias + residual + fused LayerNorm -> d_out
// ---------------------------------------------------------------------------

#define NTOK 16384
#define SEG  512
#define DQ   32
#define NG   256
#define SCALE 0.2550353055731662f   // log2(e)/sqrt(32)

typedef __half f16;

__device__ f16 g_qh[NG * SEG * DQ];
__device__ f16 g_zh[NG * SEG * DQ];
__device__ f16 g_xh[NTOK * 256];
__device__ f16 g_oh[NTOK * 256];
__device__ f16 g_wqh[256 * 256];
__device__ f16 g_fh[256 * 256];

// ---------------- helpers ----------------
__device__ __forceinline__ uint32_t sptr(const void* p) {
    return (uint32_t)__cvta_generic_to_shared(p);
}
__device__ __forceinline__ void ldsm4(uint32_t& r0, uint32_t& r1, uint32_t& r2,
                                      uint32_t& r3, uint32_t a) {
    asm volatile("ldmatrix.sync.aligned.m8n8.x4.shared.b16 {%0,%1,%2,%3}, [%4];"
                 : "=r"(r0), "=r"(r1), "=r"(r2), "=r"(r3) : "r"(a));
}
__device__ __forceinline__ void ldsm4t(uint32_t& r0, uint32_t& r1, uint32_t& r2,
                                       uint32_t& r3, uint32_t a) {
    asm volatile("ldmatrix.sync.aligned.m8n8.x4.trans.shared.b16 {%0,%1,%2,%3}, [%4];"
                 : "=r"(r0), "=r"(r1), "=r"(r2), "=r"(r3) : "r"(a));
}
__device__ __forceinline__ void mma16816(float* d, const uint32_t* a,
                                         uint32_t b0, uint32_t b1) {
    asm volatile(
        "mma.sync.aligned.m16n8k16.row.col.f32.f16.f16.f32 "
        "{%0,%1,%2,%3}, {%4,%5,%6,%7}, {%8,%9}, {%0,%1,%2,%3};"
        : "+f"(d[0]), "+f"(d[1]), "+f"(d[2]), "+f"(d[3])
        : "r"(a[0]), "r"(a[1]), "r"(a[2]), "r"(a[3]), "r"(b0), "r"(b1));
}
__device__ __forceinline__ uint32_t pack_f16(float x, float y) {
    __half2 h = __floats2half2_rn(x, y);
    return *(uint32_t*)&h;
}
__device__ __forceinline__ float ex2f(float x) {
    float r;
    asm("ex2.approx.f32 %0, %1;" : "=f"(r) : "f"(x));
    return r;
}
__device__ __forceinline__ void cpasync16(uint32_t dst, const void* src) {
    asm volatile("cp.async.ca.shared.global [%0], [%1], 16;" :: "r"(dst), "l"(src));
}

// ---------------- prep: fp32 -> fp16 planes ----------------
__global__ __launch_bounds__(256) void prep(const float* __restrict__ z,
                                            const float* __restrict__ x,
                                            const float* __restrict__ wq,
                                            const float* __restrict__ fcw) {
    int blk = blockIdx.x;
    const float* src;
    f16* dh;
    int i;
    if (blk < 4096)      { src = z;   dh = g_zh;  i = blk * 256 + threadIdx.x; }
    else if (blk < 8192) { src = x;   dh = g_xh;  i = (blk - 4096) * 256 + threadIdx.x; }
    else if (blk < 8256) { src = wq;  dh = g_wqh; i = (blk - 8192) * 256 + threadIdx.x; }
    else                 { src = fcw; dh = g_fh;  i = (blk - 8256) * 256 + threadIdx.x; }
    float4 v = ((const float4*)src)[i];
    ((uint2*)dh)[i] = make_uint2(pack_f16(v.x, v.y), pack_f16(v.z, v.w));
}

// ---------------------------------------------------------------------------
// gemm0: q-projection, 1-term fp16. 128x128 tile, 256 thr (8 warps 2x4,
// warp 64x32), BK=32, 2-stage cp.async, 2 smem planes.
// out = (acc + bias) * SCALE -> q plane, per-group layout.
// ---------------------------------------------------------------------------
#define G0_P (128 * 40)                 // f16 elems per plane per stage
#define G0_SMEM (2 * 2 * G0_P * 2)      // 40960

__global__ __launch_bounds__(256, 2) void gemm0(
    const f16* __restrict__ Ah_g, const f16* __restrict__ Wh_g,
    const float* __restrict__ bias)
{
    extern __shared__ char smem_raw[];
    f16* pl[2];
    pl[0] = (f16*)smem_raw;           // Ah [2][128][40]
    pl[1] = pl[0] + 2 * G0_P;         // Wh

    const int rb = blockIdx.y * 128, cb = blockIdx.x * 128;
    const int tid = threadIdx.x, lane = tid & 31, w = tid >> 5;
    const int wmi = w & 1, wn = w >> 1;

    const f16* gsrc[2] = { Ah_g, Wh_g };
    const int gbase[2] = { rb, cb };

    auto issue = [&](int kt, int buf) {
#pragma unroll
        for (int u = 0; u < 4; u++) {
            int idx = tid + u * 256;          // 1024 16B chunks
            int plane = idx >> 9, rem = idx & 511;
            int row = rem >> 2, q = (rem & 3) * 8;
            const f16* srcp = gsrc[plane] + (size_t)(gbase[plane] + row) * 256 + kt * 32 + q;
            cpasync16(sptr(pl[plane] + buf * G0_P + row * 40 + q), srcp);
        }
        asm volatile("cp.async.commit_group;");
    };

    float acc[4][4][4];
#pragma unroll
    for (int i = 0; i < 4; i++)
#pragma unroll
        for (int j = 0; j < 4; j++)
#pragma unroll
            for (int k = 0; k < 4; k++) acc[i][j][k] = 0.f;

    issue(0, 0);
    asm volatile("cp.async.wait_group 0;");
    __syncthreads();

#pragma unroll 1
    for (int kt = 0; kt < 8; kt++) {
        const int buf = kt & 1;
        if (kt < 7) issue(kt + 1, buf ^ 1);
        f16* Ah = pl[0] + buf * G0_P;
        f16* Wh = pl[1] + buf * G0_P;
#pragma unroll
        for (int ks = 0; ks < 2; ks++) {
            uint32_t bh[2][4];
#pragma unroll
            for (int p = 0; p < 2; p++) {
                int row = wn * 32 + p * 16 + ((lane >> 4) << 3) + (lane & 7);
                int kk = ks * 16 + ((lane >> 3) & 1) * 8;
                ldsm4(bh[p][0], bh[p][1], bh[p][2], bh[p][3], sptr(&Wh[row * 40 + kk]));
            }
#pragma unroll
            for (int mt = 0; mt < 4; mt++) {
                int row = wmi * 64 + mt * 16 + (lane & 15);
                int kk = ks * 16 + (lane >> 4) * 8;
                uint32_t ah[4];
                ldsm4(ah[0], ah[1], ah[2], ah[3], sptr(&Ah[row * 40 + kk]));
#pragma unroll
                for (int nt = 0; nt < 4; nt++) {
                    int p = nt >> 1, q = (nt & 1) * 2;
                    mma16816(acc[mt][nt], ah, bh[p][q], bh[p][q + 1]);
                }
            }
        }
        asm volatile("cp.async.wait_group 0;");
        __syncthreads();
    }

#pragma unroll
    for (int mt = 0; mt < 4; mt++) {
#pragma unroll
        for (int nt = 0; nt < 4; nt++) {
            int col = cb + wn * 32 + nt * 8 + 2 * (lane & 3);
            int r0 = rb + wmi * 64 + mt * 16 + (lane >> 2);
            float b0 = bias[col], b1 = bias[col + 1];
            float v0 = (acc[mt][nt][0] + b0) * SCALE;
            float v1 = (acc[mt][nt][1] + b1) * SCALE;
            float v2 = (acc[mt][nt][2] + b0) * SCALE;
            float v3 = (acc[mt][nt][3] + b1) * SCALE;
            int h = col >> 5, d = col & 31;
            {
                int b = r0 >> 12, s = (r0 >> 3) & 511, vv = r0 & 7;
                int dst = (((h << 3) + vv) * 4 + b) * (SEG * DQ) + s * DQ + d;
                *(uint32_t*)&g_qh[dst] = pack_f16(v0, v1);
            }
            {
                int r1 = r0 + 8;
                int b = r1 >> 12, s = (r1 >> 3) & 511, vv = r1 & 7;
                int dst = (((h << 3) + vv) * 4 + b) * (SEG * DQ) + s * DQ + d;
                *(uint32_t*)&g_qh[dst] = pack_f16(v2, v3);
            }
        }
    }
}

// ---------------------------------------------------------------------------
// gemm1: fc (1-term fp16) + bias + residual + fused LN. Tile 128 x 256
// (full row -> complete LN stats), 512 thr (2x8 warps), BK=32, 2-stage.
// ---------------------------------------------------------------------------
#define G1_A (128 * 40)
#define G1_W (256 * 40)
#define G1_SMEM ((2 * G1_A + 2 * G1_W) * 2)   // 61440

__global__ __launch_bounds__(512, 1) void gemm1(
    const f16* __restrict__ Ah_g, const f16* __restrict__ Wh_g,
    const float* __restrict__ bias, const float* __restrict__ resid,
    const float* __restrict__ gamma, const float* __restrict__ beta,
    float* __restrict__ Cp)
{
    extern __shared__ char smem_raw[];
    f16* Ahp = (f16*)smem_raw;          // [2][128][40]
    f16* Whp = Ahp + 2 * G1_A;          // [2][256][40]

    const int rb = blockIdx.x * 128;
    const int tid = threadIdx.x, lane = tid & 31, w = tid >> 5;
    const int wmi = w & 1, wn = w >> 1;   // 2 x 8

    auto issue = [&](int kt, int buf) {
        if (tid < 512) {   // A: 512 chunks
            int row = tid >> 2, q = (tid & 3) * 8;
            cpasync16(sptr(Ahp + buf * G1_A + row * 40 + q),
                      Ah_g + (size_t)(rb + row) * 256 + kt * 32 + q);
        }
#pragma unroll
        for (int u = 0; u < 2; u++) {      // W: 1024 chunks
            int idx = tid + u * 512;
            int row = idx >> 2, q = (idx & 3) * 8;
            cpasync16(sptr(Whp + buf * G1_W + row * 40 + q),
                      Wh_g + (size_t)row * 256 + kt * 32 + q);
        }
        asm volatile("cp.async.commit_group;");
    };

    float acc[4][4][4];
#pragma unroll
    for (int i = 0; i < 4; i++)
#pragma unroll
        for (int j = 0; j < 4; j++)
#pragma unroll
            for (int k = 0; k < 4; k++) acc[i][j][k] = 0.f;

    issue(0, 0);
    asm volatile("cp.async.wait_group 0;");
    __syncthreads();

#pragma unroll 1
    for (int kt = 0; kt < 8; kt++) {
        const int buf = kt & 1;
        if (kt < 7) issue(kt + 1, buf ^ 1);
        f16* Ah = Ahp + buf * G1_A;
        f16* Wh = Whp + buf * G1_W;
#pragma unroll
        for (int ks = 0; ks < 2; ks++) {
            uint32_t bh[2][4];
#pragma unroll
            for (int p = 0; p < 2; p++) {
                int row = wn * 32 + p * 16 + ((lane >> 4) << 3) + (lane & 7);
                int kk = ks * 16 + ((lane >> 3) & 1) * 8;
                ldsm4(bh[p][0], bh[p][1], bh[p][2], bh[p][3], sptr(&Wh[row * 40 + kk]));
            }
#pragma unroll
            for (int mt = 0; mt < 4; mt++) {
                int row = wmi * 64 + mt * 16 + (lane & 15);
                int kk = ks * 16 + (lane >> 4) * 8;
                uint32_t ah[4];
                ldsm4(ah[0], ah[1], ah[2], ah[3], sptr(&Ah[row * 40 + kk]));
#pragma unroll
                for (int nt = 0; nt < 4; nt++) {
                    int p = nt >> 1, q = (nt & 1) * 2;
                    mma16816(acc[mt][nt], ah, bh[p][q], bh[p][q + 1]);
                }
            }
        }
        asm volatile("cp.async.wait_group 0;");
        __syncthreads();
    }

    // bias + residual + fused LayerNorm over full 256-wide rows
    float2* red = (float2*)smem_raw;                  // [128][8]
    float* mus = (float*)(smem_raw + 8192);           // [128]
    float* rss = (float*)(smem_raw + 8192 + 512);     // [128]

#pragma unroll
    for (int mt = 0; mt < 4; mt++) {
        float s0 = 0.f, q0 = 0.f, s1 = 0.f, q1 = 0.f;
        int rl = wmi * 64 + mt * 16 + (lane >> 2);
#pragma unroll
        for (int nt = 0; nt < 4; nt++) {
            int col = wn * 32 + nt * 8 + 2 * (lane & 3);
            float b0 = bias[col], b1 = bias[col + 1];
            float2 rx0 = *(const float2*)&resid[(size_t)(rb + rl) * 256 + col];
            float2 rx1 = *(const float2*)&resid[(size_t)(rb + rl + 8) * 256 + col];
            acc[mt][nt][0] += b0 + rx0.x;
            acc[mt][nt][1] += b1 + rx0.y;
            acc[mt][nt][2] += b0 + rx1.x;
            acc[mt][nt][3] += b1 + rx1.y;
            s0 += acc[mt][nt][0] + acc[mt][nt][1];
            q0 += acc[mt][nt][0] * acc[mt][nt][0] + acc[mt][nt][1] * acc[mt][nt][1];
            s1 += acc[mt][nt][2] + acc[mt][nt][3];
            q1 += acc[mt][nt][2] * acc[mt][nt][2] + acc[mt][nt][3] * acc[mt][nt][3];
        }
#pragma unroll
        for (int o = 1; o <= 2; o <<= 1) {
            s0 += __shfl_xor_sync(0xffffffffu, s0, o);
            q0 += __shfl_xor_sync(0xffffffffu, q0, o);
            s1 += __shfl_xor_sync(0xffffffffu, s1, o);
            q1 += __shfl_xor_sync(0xffffffffu, q1, o);
        }
        if ((lane & 3) == 0) {
            red[rl * 8 + wn] = make_float2(s0, q0);
            red[(rl + 8) * 8 + wn] = make_float2(s1, q1);
        }
    }
    __syncthreads();
    if (tid < 128) {
        float s = 0.f, q = 0.f;
#pragma unroll
        for (int j = 0; j < 8; j++) {
            float2 p = red[tid * 8 + j];
            s += p.x;
            q += p.y;
        }
        float mu = s * (1.f / 256.f);
        float var = q * (1.f / 256.f) - mu * mu;
        mus[tid] = mu;
        rss[tid] = rsqrtf(var + 1e-5f);
    }
    __syncthreads();
#pragma unroll
    for (int nt = 0; nt < 4; nt++) {
        int col = wn * 32 + nt * 8 + 2 * (lane & 3);
        float g0 = gamma[col], g1 = gamma[col + 1];
        float be0 = beta[col], be1 = beta[col + 1];
#pragma unroll
        for (int mt = 0; mt < 4; mt++) {
            int rl = wmi * 64 + mt * 16 + (lane >> 2);
            float mu0 = mus[rl], rs0 = rss[rl];
            float mu1 = mus[rl + 8], rs1 = rss[rl + 8];
            float2 o0 = { (acc[mt][nt][0] - mu0) * rs0 * g0 + be0,
                          (acc[mt][nt][1] - mu0) * rs0 * g1 + be1 };
            float2 o1 = { (acc[mt][nt][2] - mu1) * rs1 * g0 + be0,
                          (acc[mt][nt][3] - mu1) * rs1 * g1 + be1 };
            *(float2*)&Cp[(size_t)(rb + rl) * 256 + col] = o0;
            *(float2*)&Cp[(size_t)(rb + rl + 8) * 256 + col] = o1;
        }
    }
}

// ---------------------------------------------------------------------------
// Attention: 2 CTAs/group (256 query rows), 256 thr (8 warps x 32 rows).
// z fp16 in smem (40KB). MMA1 (qh x zh), ex2 softmax, MMA2 (P x zh).
// Pipelined softmax(ct)/MMA1(ct+1)/MMA2(ct). Output -> o plane fp16.
// ---------------------------------------------------------------------------
struct AttnCtx {
    f16* zh;
    int lane;
    uint32_t qfh[2][2][4];
};

__device__ __forceinline__ void attn_mma1(AttnCtx& c, int ct, float s[2][2][4]) {
#pragma unroll
    for (int i = 0; i < 2; i++)
#pragma unroll
        for (int j = 0; j < 2; j++)
#pragma unroll
            for (int k = 0; k < 4; k++) s[i][j][k] = 0.f;
    const int t0 = ct * 16;
#pragma unroll
    for (int ks = 0; ks < 2; ks++) {
        int zr = t0 + ((c.lane >> 4) << 3) + (c.lane & 7);
        int zk = ks * 16 + ((c.lane >> 3) & 1) * 8;
        uint32_t zbh[4];
        ldsm4(zbh[0], zbh[1], zbh[2], zbh[3], sptr(&c.zh[zr * 40 + zk]));
#pragma unroll
        for (int mt = 0; mt < 2; mt++)
#pragma unroll
            for (int nt = 0; nt < 2; nt++)
                mma16816(s[mt][nt], c.qfh[mt][ks], zbh[nt * 2], zbh[nt * 2 + 1]);
    }
}

__device__ __forceinline__ void attn_softmax(float s[2][2][4], uint32_t pah[2][4],
                                             float dn[2][2]) {
#pragma unroll
    for (int mt = 0; mt < 2; mt++)
#pragma unroll
        for (int nt = 0; nt < 2; nt++) {
            float p0 = ex2f(s[mt][nt][0]);
            float p1 = ex2f(s[mt][nt][1]);
            float p2 = ex2f(s[mt][nt][2]);
            float p3 = ex2f(s[mt][nt][3]);
            dn[mt][0] += p0 + p1;
            dn[mt][1] += p2 + p3;
            pah[mt][nt * 2] = pack_f16(p0, p1);
            pah[mt][nt * 2 + 1] = pack_f16(p2, p3);
        }
}

__device__ __forceinline__ void attn_mma2(AttnCtx& c, int ct, uint32_t pah[2][4],
                                          float o[2][4][4]) {
    const int t0 = ct * 16;
#pragma unroll
    for (int dp = 0; dp < 2; dp++) {
        int zr = t0 + (((c.lane >> 3) & 1) << 3) + (c.lane & 7);
        int zc = dp * 16 + (c.lane >> 4) * 8;
        uint32_t zth[4];
        ldsm4t(zth[0], zth[1], zth[2], zth[3], sptr(&c.zh[zr * 40 + zc]));
#pragma unroll
        for (int mt = 0; mt < 2; mt++)
#pragma unroll
            for (int nt = 0; nt < 2; nt++)
                mma16816(o[mt][dp * 2 + nt], pah[mt], zth[nt * 2], zth[nt * 2 + 1]);
    }
}

__global__ __launch_bounds__(256, 2) void attn_mma() {
    extern __shared__ __align__(16) f16 zsm[];
    AttnCtx c;
    c.zh = zsm;   // [512][40]

    const int g = blockIdx.x >> 1, half = blockIdx.x & 1;
    const int tid = threadIdx.x, w = tid >> 5;
    c.lane = tid & 31;
    const int lane = c.lane;
    const int h = g >> 5, v = (g >> 2) & 7, b = g & 3;

    const f16* zph = g_zh + (size_t)g * SEG * DQ;
#pragma unroll
    for (int u = 0; u < 8; u++) {
        int idx = tid + u * 256;
        int row = idx >> 2, qq = idx & 3;
        *(uint4*)&c.zh[row * 40 + qq * 8] = *(const uint4*)&zph[row * 32 + qq * 8];
    }

    const f16* qph = g_qh + (size_t)g * SEG * DQ;
    const int m0 = half * 256 + w * 32;
#pragma unroll
    for (int mt = 0; mt < 2; mt++)
#pragma unroll
        for (int ks = 0; ks < 2; ks++) {
            int row = m0 + mt * 16 + (lane >> 2);
            int kk = ks * 16 + 2 * (lane & 3);
            c.qfh[mt][ks][0] = *(const uint32_t*)&qph[row * 32 + kk];
            c.qfh[mt][ks][1] = *(const uint32_t*)&qph[(row + 8) * 32 + kk];
            c.qfh[mt][ks][2] = *(const uint32_t*)&qph[row * 32 + kk + 8];
            c.qfh[mt][ks][3] = *(const uint32_t*)&qph[(row + 8) * 32 + kk + 8];
        }

    float o[2][4][4];
#pragma unroll
    for (int i = 0; i < 2; i++)
#pragma unroll
        for (int j = 0; j < 4; j++)
#pragma unroll
            for (int k = 0; k < 4; k++) o[i][j][k] = 0.f;
    float dn[2][2] = {{0.f, 0.f}, {0.f, 0.f}};

    __syncthreads();

    float s[2][2][4];
    attn_mma1(c, 0, s);

#pragma unroll 1
    for (int ct = 0; ct < 31; ct++) {
        uint32_t pah[2][4];
        attn_softmax(s, pah, dn);
        float s2[2][2][4];
        attn_mma1(c, ct + 1, s2);
        attn_mma2(c, ct, pah, o);
#pragma unroll
        for (int i = 0; i < 2; i++)
#pragma unroll
            for (int j = 0; j < 2; j++)
#pragma unroll
                for (int k = 0; k < 4; k++) s[i][j][k] = s2[i][j][k];
    }
    {
        uint32_t pah[2][4];
        attn_softmax(s, pah, dn);
        attn_mma2(c, 31, pah, o);
    }

    float inv[2][2];
#pragma unroll
    for (int mt = 0; mt < 2; mt++)
#pragma unroll
        for (int rh = 0; rh < 2; rh++) {
            float d = dn[mt][rh];
            d += __shfl_xor_sync(0xffffffffu, d, 1);
            d += __shfl_xor_sync(0xffffffffu, d, 2);
            inv[mt][rh] = __fdividef(1.f, d);
        }

    // store O plane, token-major
#pragma unroll
    for (int mt = 0; mt < 2; mt++) {
        int s0 = m0 + mt * 16 + (lane >> 2);
        int r0 = ((b * SEG + s0) * 8) + v;
        int r1 = ((b * SEG + s0 + 8) * 8) + v;
#pragma unroll
        for (int n = 0; n < 4; n++) {
            int col = h * 32 + n * 8 + 2 * (lane & 3);
            *(uint32_t*)&g_oh[(size_t)r0 * 256 + col] =
                pack_f16(o[mt][n][0] * inv[mt][0], o[mt][n][1] * inv[mt][0]);
            *(uint32_t*)&g_oh[(size_t)r1 * 256 + col] =
                pack_f16(o[mt][n][2] * inv[mt][1], o[mt][n][3] * inv[mt][1]);
        }
    }
}

// ---------------------------------------------------------------------------

extern "C" void kernel_launch(void* const* d_in, const int* in_sizes, int n_in,
                              void* d_out, int out_size)
{
    const float* x     = (const float*)d_in[0];
    const float* z     = (const float*)d_in[1];
    const float* wq    = (const float*)d_in[2];
    const float* wqb   = (const float*)d_in[3];
    const float* fcw   = (const float*)d_in[4];
    const float* fcb   = (const float*)d_in[5];
    const float* gamma = (const float*)d_in[6];
    const float* beta  = (const float*)d_in[7];
    float* y = (float*)d_out;

    static f16 *xh_p = nullptr, *oh_p, *wqh_p, *fh_p;
    if (!xh_p) {
        cudaGetSymbolAddress((void**)&xh_p, g_xh);
        cudaGetSymbolAddress((void**)&oh_p, g_oh);
        cudaGetSymbolAddress((void**)&wqh_p, g_wqh);
        cudaGetSymbolAddress((void**)&fh_p, g_fh);
        cudaFuncSetAttribute(gemm0, cudaFuncAttributeMaxDynamicSharedMemorySize, G0_SMEM);
        cudaFuncSetAttribute(gemm1, cudaFuncAttributeMaxDynamicSharedMemorySize, G1_SMEM);
        cudaFuncSetAttribute(attn_mma, cudaFuncAttributeMaxDynamicSharedMemorySize, 512 * 40 * 2);
    }

    prep<<<8320, 256>>>(z, x, wq, fcw);
    dim3 g0grid(2, 128);
    gemm0<<<g0grid, 256, G0_SMEM>>>(xh_p, wqh_p, wqb);
    attn_mma<<<NG * 2, 256, 512 * 40 * 2>>>();
    gemm1<<<128, 512, G1_SMEM>>>(oh_p, fh_p, fcb, x, gamma, beta, y);
}

// round 9
// speedup vs baseline: 5.2125x; 1.0359x over previous
#include <cuda_runtime.h>
#include <cuda_fp16.h>
#include <cstdint>

// ---------------------------------------------------------------------------
// bs=4 seg=512 nv=8 h=8 dq=32 din=256; tokens=16384, groups=256
// ALL-FP16 datapath.
//  prep  : x, z, Wq, fc -> fp16 planes
//  gemm0 : q = (x@WqT + b)*log2e/temp -> per-group q plane (128x128, occ2)
//  attn  : 2 CTAs/group; MMA1, ex2.f16x2 softmax, MMA2 -> o plane
//  gemm1 : fc + bias + residual + fused LN (64x256 tile, 256thr, occ2)
// ---------------------------------------------------------------------------

#define NTOK 16384
#define SEG  512
#define DQ   32
#define NG   256
#define SCALE 0.2550353055731662f   // log2(e)/sqrt(32)

typedef __half f16;

__device__ f16 g_qh[NG * SEG * DQ];
__device__ f16 g_zh[NG * SEG * DQ];
__device__ f16 g_xh[NTOK * 256];
__device__ f16 g_oh[NTOK * 256];
__device__ f16 g_wqh[256 * 256];
__device__ f16 g_fh[256 * 256];

// ---------------- helpers ----------------
__device__ __forceinline__ uint32_t sptr(const void* p) {
    return (uint32_t)__cvta_generic_to_shared(p);
}
__device__ __forceinline__ void ldsm4(uint32_t& r0, uint32_t& r1, uint32_t& r2,
                                      uint32_t& r3, uint32_t a) {
    asm volatile("ldmatrix.sync.aligned.m8n8.x4.shared.b16 {%0,%1,%2,%3}, [%4];"
                 : "=r"(r0), "=r"(r1), "=r"(r2), "=r"(r3) : "r"(a));
}
__device__ __forceinline__ void ldsm4t(uint32_t& r0, uint32_t& r1, uint32_t& r2,
                                       uint32_t& r3, uint32_t a) {
    asm volatile("ldmatrix.sync.aligned.m8n8.x4.trans.shared.b16 {%0,%1,%2,%3}, [%4];"
                 : "=r"(r0), "=r"(r1), "=r"(r2), "=r"(r3) : "r"(a));
}
__device__ __forceinline__ void mma16816(float* d, const uint32_t* a,
                                         uint32_t b0, uint32_t b1) {
    asm volatile(
        "mma.sync.aligned.m16n8k16.row.col.f32.f16.f16.f32 "
        "{%0,%1,%2,%3}, {%4,%5,%6,%7}, {%8,%9}, {%0,%1,%2,%3};"
        : "+f"(d[0]), "+f"(d[1]), "+f"(d[2]), "+f"(d[3])
        : "r"(a[0]), "r"(a[1]), "r"(a[2]), "r"(a[3]), "r"(b0), "r"(b1));
}
__device__ __forceinline__ uint32_t pack_f16(float x, float y) {
    __half2 h = __floats2half2_rn(x, y);
    return *(uint32_t*)&h;
}
__device__ __forceinline__ uint32_t ex2_f16x2(uint32_t a) {
    uint32_t r;
    asm("ex2.approx.f16x2 %0, %1;" : "=r"(r) : "r"(a));
    return r;
}
__device__ __forceinline__ void cpasync16(uint32_t dst, const void* src) {
    asm volatile("cp.async.ca.shared.global [%0], [%1], 16;" :: "r"(dst), "l"(src));
}

// ---------------- prep: fp32 -> fp16 planes ----------------
__global__ __launch_bounds__(256) void prep(const float* __restrict__ z,
                                            const float* __restrict__ x,
                                            const float* __restrict__ wq,
                                            const float* __restrict__ fcw) {
    int blk = blockIdx.x;
    const float* src;
    f16* dh;
    int i;
    if (blk < 4096)      { src = z;   dh = g_zh;  i = blk * 256 + threadIdx.x; }
    else if (blk < 8192) { src = x;   dh = g_xh;  i = (blk - 4096) * 256 + threadIdx.x; }
    else if (blk < 8256) { src = wq;  dh = g_wqh; i = (blk - 8192) * 256 + threadIdx.x; }
    else                 { src = fcw; dh = g_fh;  i = (blk - 8256) * 256 + threadIdx.x; }
    float4 v = ((const float4*)src)[i];
    ((uint2*)dh)[i] = make_uint2(pack_f16(v.x, v.y), pack_f16(v.z, v.w));
}

// ---------------------------------------------------------------------------
// gemm0: q-projection. 128x128 tile, 256 thr (8 warps 2x4), BK=32, 2-stage,
// 2 CTAs/SM. out = (acc + bias) * SCALE -> q plane, per-group layout.
// ---------------------------------------------------------------------------
#define G0_P (128 * 40)
#define G0_SMEM (2 * 2 * G0_P * 2)      // 40960

__global__ __launch_bounds__(256, 2) void gemm0(
    const f16* __restrict__ Ah_g, const f16* __restrict__ Wh_g,
    const float* __restrict__ bias)
{
    extern __shared__ char smem_raw[];
    f16* pl[2];
    pl[0] = (f16*)smem_raw;           // Ah [2][128][40]
    pl[1] = pl[0] + 2 * G0_P;         // Wh

    const int rb = blockIdx.y * 128, cb = blockIdx.x * 128;
    const int tid = threadIdx.x, lane = tid & 31, w = tid >> 5;
    const int wmi = w & 1, wn = w >> 1;

    const f16* gsrc[2] = { Ah_g, Wh_g };
    const int gbase[2] = { rb, cb };

    auto issue = [&](int kt, int buf) {
#pragma unroll
        for (int u = 0; u < 4; u++) {
            int idx = tid + u * 256;
            int plane = idx >> 9, rem = idx & 511;
            int row = rem >> 2, q = (rem & 3) * 8;
            const f16* srcp = gsrc[plane] + (size_t)(gbase[plane] + row) * 256 + kt * 32 + q;
            cpasync16(sptr(pl[plane] + buf * G0_P + row * 40 + q), srcp);
        }
        asm volatile("cp.async.commit_group;");
    };

    float acc[4][4][4];
#pragma unroll
    for (int i = 0; i < 4; i++)
#pragma unroll
        for (int j = 0; j < 4; j++)
#pragma unroll
            for (int k = 0; k < 4; k++) acc[i][j][k] = 0.f;

    issue(0, 0);
    asm volatile("cp.async.wait_group 0;");
    __syncthreads();

#pragma unroll 1
    for (int kt = 0; kt < 8; kt++) {
        const int buf = kt & 1;
        if (kt < 7) issue(kt + 1, buf ^ 1);
        f16* Ah = pl[0] + buf * G0_P;
        f16* Wh = pl[1] + buf * G0_P;
#pragma unroll
        for (int ks = 0; ks < 2; ks++) {
            uint32_t bh[2][4];
#pragma unroll
            for (int p = 0; p < 2; p++) {
                int row = wn * 32 + p * 16 + ((lane >> 4) << 3) + (lane & 7);
                int kk = ks * 16 + ((lane >> 3) & 1) * 8;
                ldsm4(bh[p][0], bh[p][1], bh[p][2], bh[p][3], sptr(&Wh[row * 40 + kk]));
            }
#pragma unroll
            for (int mt = 0; mt < 4; mt++) {
                int row = wmi * 64 + mt * 16 + (lane & 15);
                int kk = ks * 16 + (lane >> 4) * 8;
                uint32_t ah[4];
                ldsm4(ah[0], ah[1], ah[2], ah[3], sptr(&Ah[row * 40 + kk]));
#pragma unroll
                for (int nt = 0; nt < 4; nt++) {
                    int p = nt >> 1, q = (nt & 1) * 2;
                    mma16816(acc[mt][nt], ah, bh[p][q], bh[p][q + 1]);
                }
            }
        }
        asm volatile("cp.async.wait_group 0;");
        __syncthreads();
    }

#pragma unroll
    for (int mt = 0; mt < 4; mt++) {
#pragma unroll
        for (int nt = 0; nt < 4; nt++) {
            int col = cb + wn * 32 + nt * 8 + 2 * (lane & 3);
            int r0 = rb + wmi * 64 + mt * 16 + (lane >> 2);
            float b0 = bias[col], b1 = bias[col + 1];
            float v0 = (acc[mt][nt][0] + b0) * SCALE;
            float v1 = (acc[mt][nt][1] + b1) * SCALE;
            float v2 = (acc[mt][nt][2] + b0) * SCALE;
            float v3 = (acc[mt][nt][3] + b1) * SCALE;
            int h = col >> 5, d = col & 31;
            {
                int b = r0 >> 12, s = (r0 >> 3) & 511, vv = r0 & 7;
                int dst = (((h << 3) + vv) * 4 + b) * (SEG * DQ) + s * DQ + d;
                *(uint32_t*)&g_qh[dst] = pack_f16(v0, v1);
            }
            {
                int r1 = r0 + 8;
                int b = r1 >> 12, s = (r1 >> 3) & 511, vv = r1 & 7;
                int dst = (((h << 3) + vv) * 4 + b) * (SEG * DQ) + s * DQ + d;
                *(uint32_t*)&g_qh[dst] = pack_f16(v2, v3);
            }
        }
    }
}

// ---------------------------------------------------------------------------
// gemm1: fc + bias + residual + fused LN. Tile 64 rows x 256 cols (full row
// per CTA -> complete LN stats), 256 thr (8 warps 2x4, warp 32x64), BK=32,
// 2-stage cp.async, 2 CTAs/SM for stall overlap. Grid 256 = one wave.
// ---------------------------------------------------------------------------
#define G1_A (64 * 40)
#define G1_W (256 * 40)
#define G1_SMEM ((2 * G1_A + 2 * G1_W) * 2)   // 51200

__global__ __launch_bounds__(256, 2) void gemm1(
    const f16* __restrict__ Ah_g, const f16* __restrict__ Wh_g,
    const float* __restrict__ bias, const float* __restrict__ resid,
    const float* __restrict__ gamma, const float* __restrict__ beta,
    float* __restrict__ Cp)
{
    extern __shared__ char smem_raw[];
    f16* Ahp = (f16*)smem_raw;          // [2][64][40]
    f16* Whp = Ahp + 2 * G1_A;          // [2][256][40]

    const int rb = blockIdx.x * 64;
    const int tid = threadIdx.x, lane = tid & 31, w = tid >> 5;
    const int wmi = w & 1, wn = w >> 1;   // 2 (row) x 4 (col)

    auto issue = [&](int kt, int buf) {
#pragma unroll
        for (int u = 0; u < 5; u++) {      // 1280 16B chunks: 256 A + 1024 W
            int idx = tid + u * 256;
            if (idx < 256) {
                int row = idx >> 2, q = (idx & 3) * 8;
                cpasync16(sptr(Ahp + buf * G1_A + row * 40 + q),
                          Ah_g + (size_t)(rb + row) * 256 + kt * 32 + q);
            } else {
                int i2 = idx - 256;
                int row = i2 >> 2, q = (i2 & 3) * 8;
                cpasync16(sptr(Whp + buf * G1_W + row * 40 + q),
                          Wh_g + (size_t)row * 256 + kt * 32 + q);
            }
        }
        asm volatile("cp.async.commit_group;");
    };

    float acc[2][8][4];
#pragma unroll
    for (int i = 0; i < 2; i++)
#pragma unroll
        for (int j = 0; j < 8; j++)
#pragma unroll
            for (int k = 0; k < 4; k++) acc[i][j][k] = 0.f;

    issue(0, 0);
    asm volatile("cp.async.wait_group 0;");
    __syncthreads();

#pragma unroll 1
    for (int kt = 0; kt < 8; kt++) {
        const int buf = kt & 1;
        if (kt < 7) issue(kt + 1, buf ^ 1);
        f16* Ah = Ahp + buf * G1_A;
        f16* Wh = Whp + buf * G1_W;
#pragma unroll
        for (int ks = 0; ks < 2; ks++) {
            uint32_t bh[4][4];
#pragma unroll
            for (int p = 0; p < 4; p++) {
                int row = wn * 64 + p * 16 + ((lane >> 4) << 3) + (lane & 7);
                int kk = ks * 16 + ((lane >> 3) & 1) * 8;
                ldsm4(bh[p][0], bh[p][1], bh[p][2], bh[p][3], sptr(&Wh[row * 40 + kk]));
            }
#pragma unroll
            for (int mt = 0; mt < 2; mt++) {
                int row = wmi * 32 + mt * 16 + (lane & 15);
                int kk = ks * 16 + (lane >> 4) * 8;
                uint32_t ah[4];
                ldsm4(ah[0], ah[1], ah[2], ah[3], sptr(&Ah[row * 40 + kk]));
#pragma unroll
                for (int nt = 0; nt < 8; nt++) {
                    int p = nt >> 1, q = (nt & 1) * 2;
                    mma16816(acc[mt][nt], ah, bh[p][q], bh[p][q + 1]);
                }
            }
        }
        asm volatile("cp.async.wait_group 0;");
        __syncthreads();
    }

    // bias + residual + fused LayerNorm over full 256-wide rows
    float2* red = (float2*)smem_raw;                  // [64][4]
    float* mus = (float*)(smem_raw + 4096);           // [64]
    float* rss = (float*)(smem_raw + 4096 + 256);     // [64]

#pragma unroll
    for (int mt = 0; mt < 2; mt++) {
        float s0 = 0.f, q0 = 0.f, s1 = 0.f, q1 = 0.f;
        int rl = wmi * 32 + mt * 16 + (lane >> 2);
#pragma unroll
        for (int nt = 0; nt < 8; nt++) {
            int col = wn * 64 + nt * 8 + 2 * (lane & 3);
            float b0 = bias[col], b1 = bias[col + 1];
            float2 rx0 = *(const float2*)&resid[(size_t)(rb + rl) * 256 + col];
            float2 rx1 = *(const float2*)&resid[(size_t)(rb + rl + 8) * 256 + col];
            acc[mt][nt][0] += b0 + rx0.x;
            acc[mt][nt][1] += b1 + rx0.y;
            acc[mt][nt][2] += b0 + rx1.x;
            acc[mt][nt][3] += b1 + rx1.y;
            s0 += acc[mt][nt][0] + acc[mt][nt][1];
            q0 += acc[mt][nt][0] * acc[mt][nt][0] + acc[mt][nt][1] * acc[mt][nt][1];
            s1 += acc[mt][nt][2] + acc[mt][nt][3];
            q1 += acc[mt][nt][2] * acc[mt][nt][2] + acc[mt][nt][3] * acc[mt][nt][3];
        }
#pragma unroll
        for (int o = 1; o <= 2; o <<= 1) {
            s0 += __shfl_xor_sync(0xffffffffu, s0, o);
            q0 += __shfl_xor_sync(0xffffffffu, q0, o);
            s1 += __shfl_xor_sync(0xffffffffu, s1, o);
            q1 += __shfl_xor_sync(0xffffffffu, q1, o);
        }
        if ((lane & 3) == 0) {
            red[rl * 4 + wn] = make_float2(s0, q0);
            red[(rl + 8) * 4 + wn] = make_float2(s1, q1);
        }
    }
    __syncthreads();
    if (tid < 64) {
        float s = 0.f, q = 0.f;
#pragma unroll
        for (int j = 0; j < 4; j++) {
            float2 p = red[tid * 4 + j];
            s += p.x;
            q += p.y;
        }
        float mu = s * (1.f / 256.f);
        float var = q * (1.f / 256.f) - mu * mu;
        mus[tid] = mu;
        rss[tid] = rsqrtf(var + 1e-5f);
    }
    __syncthreads();
#pragma unroll
    for (int nt = 0; nt < 8; nt++) {
        int col = wn * 64 + nt * 8 + 2 * (lane & 3);
        float g0 = gamma[col], g1 = gamma[col + 1];
        float be0 = beta[col], be1 = beta[col + 1];
#pragma unroll
        for (int mt = 0; mt < 2; mt++) {
            int rl = wmi * 32 + mt * 16 + (lane >> 2);
            float mu0 = mus[rl], rs0 = rss[rl];
            float mu1 = mus[rl + 8], rs1 = rss[rl + 8];
            float2 o0 = { (acc[mt][nt][0] - mu0) * rs0 * g0 + be0,
                          (acc[mt][nt][1] - mu0) * rs0 * g1 + be1 };
            float2 o1 = { (acc[mt][nt][2] - mu1) * rs1 * g0 + be0,
                          (acc[mt][nt][3] - mu1) * rs1 * g1 + be1 };
            *(float2*)&Cp[(size_t)(rb + rl) * 256 + col] = o0;
            *(float2*)&Cp[(size_t)(rb + rl + 8) * 256 + col] = o1;
        }
    }
}

// ---------------------------------------------------------------------------
// Attention: 2 CTAs/group (256 query rows), 256 thr (8 warps x 32 rows).
// z fp16 in smem (40KB). MMA1, ex2.approx.f16x2 softmax (p already packed
// as the MMA2 A-fragment), MMA2. Pipelined softmax(ct)/MMA1(ct+1)/MMA2(ct).
// ---------------------------------------------------------------------------
struct AttnCtx {
    f16* zh;
    int lane;
    uint32_t qfh[2][2][4];
};

__device__ __forceinline__ void attn_mma1(AttnCtx& c, int ct, float s[2][2][4]) {
#pragma unroll
    for (int i = 0; i < 2; i++)
#pragma unroll
        for (int j = 0; j < 2; j++)
#pragma unroll
            for (int k = 0; k < 4; k++) s[i][j][k] = 0.f;
    const int t0 = ct * 16;
#pragma unroll
    for (int ks = 0; ks < 2; ks++) {
        int zr = t0 + ((c.lane >> 4) << 3) + (c.lane & 7);
        int zk = ks * 16 + ((c.lane >> 3) & 1) * 8;
        uint32_t zbh[4];
        ldsm4(zbh[0], zbh[1], zbh[2], zbh[3], sptr(&c.zh[zr * 40 + zk]));
#pragma unroll
        for (int mt = 0; mt < 2; mt++)
#pragma unroll
            for (int nt = 0; nt < 2; nt++)
                mma16816(s[mt][nt], c.qfh[mt][ks], zbh[nt * 2], zbh[nt * 2 + 1]);
    }
}

__device__ __forceinline__ void attn_softmax(float s[2][2][4], uint32_t pah[2][4],
                                             float dn[2][2]) {
#pragma unroll
    for (int mt = 0; mt < 2; mt++) {
#pragma unroll
        for (int nt = 0; nt < 2; nt++) {
            pah[mt][nt * 2]     = ex2_f16x2(pack_f16(s[mt][nt][0], s[mt][nt][1]));
            pah[mt][nt * 2 + 1] = ex2_f16x2(pack_f16(s[mt][nt][2], s[mt][nt][3]));
        }
        // denominators: rh0 from pah[0]+pah[2], rh1 from pah[1]+pah[3]
        __half2 h0 = __hadd2(*(__half2*)&pah[mt][0], *(__half2*)&pah[mt][2]);
        __half2 h1 = __hadd2(*(__half2*)&pah[mt][1], *(__half2*)&pah[mt][3]);
        float2 f0 = __half22float2(h0);
        float2 f1 = __half22float2(h1);
        dn[mt][0] += f0.x + f0.y;
        dn[mt][1] += f1.x + f1.y;
    }
}

__device__ __forceinline__ void attn_mma2(AttnCtx& c, int ct, uint32_t pah[2][4],
                                          float o[2][4][4]) {
    const int t0 = ct * 16;
#pragma unroll
    for (int dp = 0; dp < 2; dp++) {
        int zr = t0 + (((c.lane >> 3) & 1) << 3) + (c.lane & 7);
        int zc = dp * 16 + (c.lane >> 4) * 8;
        uint32_t zth[4];
        ldsm4t(zth[0], zth[1], zth[2], zth[3], sptr(&c.zh[zr * 40 + zc]));
#pragma unroll
        for (int mt = 0; mt < 2; mt++)
#pragma unroll
            for (int nt = 0; nt < 2; nt++)
                mma16816(o[mt][dp * 2 + nt], pah[mt], zth[nt * 2], zth[nt * 2 + 1]);
    }
}

__global__ __launch_bounds__(256, 2) void attn_mma() {
    extern __shared__ __align__(16) f16 zsm[];
    AttnCtx c;
    c.zh = zsm;   // [512][40]

    const int g = blockIdx.x >> 1, half = blockIdx.x & 1;
    const int tid = threadIdx.x, w = tid >> 5;
    c.lane = tid & 31;
    const int lane = c.lane;
    const int h = g >> 5, v = (g >> 2) & 7, b = g & 3;

    const f16* zph = g_zh + (size_t)g * SEG * DQ;
#pragma unroll
    for (int u = 0; u < 8; u++) {
        int idx = tid + u * 256;
        int row = idx >> 2, qq = idx & 3;
        *(uint4*)&c.zh[row * 40 + qq * 8] = *(const uint4*)&zph[row * 32 + qq * 8];
    }

    const f16* qph = g_qh + (size_t)g * SEG * DQ;
    const int m0 = half * 256 + w * 32;
#pragma unroll
    for (int mt = 0; mt < 2; mt++)
#pragma unroll
        for (int ks = 0; ks < 2; ks++) {
            int row = m0 + mt * 16 + (lane >> 2);
            int kk = ks * 16 + 2 * (lane & 3);
            c.qfh[mt][ks][0] = *(const uint32_t*)&qph[row * 32 + kk];
            c.qfh[mt][ks][1] = *(const uint32_t*)&qph[(row + 8) * 32 + kk];
            c.qfh[mt][ks][2] = *(const uint32_t*)&qph[row * 32 + kk + 8];
            c.qfh[mt][ks][3] = *(const uint32_t*)&qph[(row + 8) * 32 + kk + 8];
        }

    float o[2][4][4];
#pragma unroll
    for (int i = 0; i < 2; i++)
#pragma unroll
        for (int j = 0; j < 4; j++)
#pragma unroll
            for (int k = 0; k < 4; k++) o[i][j][k] = 0.f;
    float dn[2][2] = {{0.f, 0.f}, {0.f, 0.f}};

    __syncthreads();

    float s[2][2][4];
    attn_mma1(c, 0, s);

#pragma unroll 1
    for (int ct = 0; ct < 31; ct++) {
        uint32_t pah[2][4];
        attn_softmax(s, pah, dn);
        float s2[2][2][4];
        attn_mma1(c, ct + 1, s2);
        attn_mma2(c, ct, pah, o);
#pragma unroll
        for (int i = 0; i < 2; i++)
#pragma unroll
            for (int j = 0; j < 2; j++)
#pragma unroll
                for (int k = 0; k < 4; k++) s[i][j][k] = s2[i][j][k];
    }
    {
        uint32_t pah[2][4];
        attn_softmax(s, pah, dn);
        attn_mma2(c, 31, pah, o);
    }

    float inv[2][2];
#pragma unroll
    for (int mt = 0; mt < 2; mt++)
#pragma unroll
        for (int rh = 0; rh < 2; rh++) {
            float d = dn[mt][rh];
            d += __shfl_xor_sync(0xffffffffu, d, 1);
            d += __shfl_xor_sync(0xffffffffu, d, 2);
            inv[mt][rh] = __fdividef(1.f, d);
        }

    // store O plane, token-major
#pragma unroll
    for (int mt = 0; mt < 2; mt++) {
        int s0 = m0 + mt * 16 + (lane >> 2);
        int r0 = ((b * SEG + s0) * 8) + v;
        int r1 = ((b * SEG + s0 + 8) * 8) + v;
#pragma unroll
        for (int n = 0; n < 4; n++) {
            int col = h * 32 + n * 8 + 2 * (lane & 3);
            *(uint32_t*)&g_oh[(size_t)r0 * 256 + col] =
                pack_f16(o[mt][n][0] * inv[mt][0], o[mt][n][1] * inv[mt][0]);
            *(uint32_t*)&g_oh[(size_t)r1 * 256 + col] =
                pack_f16(o[mt][n][2] * inv[mt][1], o[mt][n][3] * inv[mt][1]);
        }
    }
}

// ---------------------------------------------------------------------------

extern "C" void kernel_launch(void* const* d_in, const int* in_sizes, int n_in,
                              void* d_out, int out_size)
{
    const float* x     = (const float*)d_in[0];
    const float* z     = (const float*)d_in[1];
    const float* wq    = (const float*)d_in[2];
    const float* wqb   = (const float*)d_in[3];
    const float* fcw   = (const float*)d_in[4];
    const float* fcb   = (const float*)d_in[5];
    const float* gamma = (const float*)d_in[6];
    const float* beta  = (const float*)d_in[7];
    float* y = (float*)d_out;

    static f16 *xh_p = nullptr, *oh_p, *wqh_p, *fh_p;
    if (!xh_p) {
        cudaGetSymbolAddress((void**)&xh_p, g_xh);
        cudaGetSymbolAddress((void**)&oh_p, g_oh);
        cudaGetSymbolAddress((void**)&wqh_p, g_wqh);
        cudaGetSymbolAddress((void**)&fh_p, g_fh);
        cudaFuncSetAttribute(gemm0, cudaFuncAttributeMaxDynamicSharedMemorySize, G0_SMEM);
        cudaFuncSetAttribute(gemm1, cudaFuncAttributeMaxDynamicSharedMemorySize, G1_SMEM);
        cudaFuncSetAttribute(attn_mma, cudaFuncAttributeMaxDynamicSharedMemorySize, 512 * 40 * 2);
    }

    prep<<<8320, 256>>>(z, x, wq, fcw);
    dim3 g0grid(2, 128);
    gemm0<<<g0grid, 256, G0_SMEM>>>(xh_p, wqh_p, wqb);
    attn_mma<<<NG * 2, 256, 512 * 40 * 2>>>();
    gemm1<<<256, 256, G1_SMEM>>>(oh_p, fh_p, fcb, x, gamma, beta, y);
}

// round 10
// speedup vs baseline: 5.3715x; 1.0305x over previous
#include <cuda_runtime.h>
#include <cuda_fp16.h>
#include <cstdint>

// ---------------------------------------------------------------------------
// bs=4 seg=512 nv=8 h=8 dq=32 din=256; tokens=16384, groups=256
// ALL-FP16 datapath.
//  prep  : x, z, Wq, fc -> fp16 planes
//  gemm0 : q = (x@WqT + b)*log2e/temp (128x128, 3-stage cp.async, occ2)
//  attn  : 4 CTAs/group (128 rows, 128 thr, occ5); MMA1, ex2.f16x2, MMA2
//  gemm1 : fc + bias + residual + fused LN (64x256, 3-stage, occ2)
// ---------------------------------------------------------------------------

#define NTOK 16384
#define SEG  512
#define DQ   32
#define NG   256
#define SCALE 0.2550353055731662f   // log2(e)/sqrt(32)

typedef __half f16;

__device__ f16 g_qh[NG * SEG * DQ];
__device__ f16 g_zh[NG * SEG * DQ];
__device__ f16 g_xh[NTOK * 256];
__device__ f16 g_oh[NTOK * 256];
__device__ f16 g_wqh[256 * 256];
__device__ f16 g_fh[256 * 256];

// ---------------- helpers ----------------
__device__ __forceinline__ uint32_t sptr(const void* p) {
    return (uint32_t)__cvta_generic_to_shared(p);
}
__device__ __forceinline__ void ldsm4(uint32_t& r0, uint32_t& r1, uint32_t& r2,
                                      uint32_t& r3, uint32_t a) {
    asm volatile("ldmatrix.sync.aligned.m8n8.x4.shared.b16 {%0,%1,%2,%3}, [%4];"
                 : "=r"(r0), "=r"(r1), "=r"(r2), "=r"(r3) : "r"(a));
}
__device__ __forceinline__ void ldsm4t(uint32_t& r0, uint32_t& r1, uint32_t& r2,
                                       uint32_t& r3, uint32_t a) {
    asm volatile("ldmatrix.sync.aligned.m8n8.x4.trans.shared.b16 {%0,%1,%2,%3}, [%4];"
                 : "=r"(r0), "=r"(r1), "=r"(r2), "=r"(r3) : "r"(a));
}
__device__ __forceinline__ void mma16816(float* d, const uint32_t* a,
                                         uint32_t b0, uint32_t b1) {
    asm volatile(
        "mma.sync.aligned.m16n8k16.row.col.f32.f16.f16.f32 "
        "{%0,%1,%2,%3}, {%4,%5,%6,%7}, {%8,%9}, {%0,%1,%2,%3};"
        : "+f"(d[0]), "+f"(d[1]), "+f"(d[2]), "+f"(d[3])
        : "r"(a[0]), "r"(a[1]), "r"(a[2]), "r"(a[3]), "r"(b0), "r"(b1));
}
__device__ __forceinline__ uint32_t pack_f16(float x, float y) {
    __half2 h = __floats2half2_rn(x, y);
    return *(uint32_t*)&h;
}
__device__ __forceinline__ uint32_t ex2_f16x2(uint32_t a) {
    uint32_t r;
    asm("ex2.approx.f16x2 %0, %1;" : "=r"(r) : "r"(a));
    return r;
}
__device__ __forceinline__ void cpasync16(uint32_t dst, const void* src) {
    asm volatile("cp.async.ca.shared.global [%0], [%1], 16;" :: "r"(dst), "l"(src));
}

// ---------------- prep: fp32 -> fp16 planes ----------------
__global__ __launch_bounds__(256) void prep(const float* __restrict__ z,
                                            const float* __restrict__ x,
                                            const float* __restrict__ wq,
                                            const float* __restrict__ fcw) {
    int blk = blockIdx.x;
    const float* src;
    f16* dh;
    int i;
    if (blk < 4096)      { src = z;   dh = g_zh;  i = blk * 256 + threadIdx.x; }
    else if (blk < 8192) { src = x;   dh = g_xh;  i = (blk - 4096) * 256 + threadIdx.x; }
    else if (blk < 8256) { src = wq;  dh = g_wqh; i = (blk - 8192) * 256 + threadIdx.x; }
    else                 { src = fcw; dh = g_fh;  i = (blk - 8256) * 256 + threadIdx.x; }
    float4 v = ((const float4*)src)[i];
    ((uint2*)dh)[i] = make_uint2(pack_f16(v.x, v.y), pack_f16(v.z, v.w));
}

// ---------------------------------------------------------------------------
// gemm0: q-projection. 128x128 tile, 256 thr (8 warps 2x4), BK=32,
// 3-stage cp.async, 2 CTAs/SM. out = (acc+bias)*SCALE -> q plane.
// ---------------------------------------------------------------------------
#define G0_P (128 * 40)
#define G0_SMEM (3 * 2 * G0_P * 2)      // 61440

__global__ __launch_bounds__(256, 2) void gemm0(
    const f16* __restrict__ Ah_g, const f16* __restrict__ Wh_g,
    const float* __restrict__ bias)
{
    extern __shared__ char smem_raw[];
    f16* pl[2];
    pl[0] = (f16*)smem_raw;           // Ah [3][128][40]
    pl[1] = pl[0] + 3 * G0_P;         // Wh

    const int rb = blockIdx.y * 128, cb = blockIdx.x * 128;
    const int tid = threadIdx.x, lane = tid & 31, w = tid >> 5;
    const int wmi = w & 1, wn = w >> 1;

    const f16* gsrc[2] = { Ah_g, Wh_g };
    const int gbase[2] = { rb, cb };

    auto issue = [&](int kt, int buf) {
#pragma unroll
        for (int u = 0; u < 4; u++) {
            int idx = tid + u * 256;
            int plane = idx >> 9, rem = idx & 511;
            int row = rem >> 2, q = (rem & 3) * 8;
            const f16* srcp = gsrc[plane] + (size_t)(gbase[plane] + row) * 256 + kt * 32 + q;
            cpasync16(sptr(pl[plane] + buf * G0_P + row * 40 + q), srcp);
        }
        asm volatile("cp.async.commit_group;");
    };

    float acc[4][4][4];
#pragma unroll
    for (int i = 0; i < 4; i++)
#pragma unroll
        for (int j = 0; j < 4; j++)
#pragma unroll
            for (int k = 0; k < 4; k++) acc[i][j][k] = 0.f;

    issue(0, 0);
    issue(1, 1);

#pragma unroll 1
    for (int kt = 0; kt < 8; kt++) {
        if (kt < 7) asm volatile("cp.async.wait_group 1;");
        else        asm volatile("cp.async.wait_group 0;");
        __syncthreads();
        if (kt < 6) issue(kt + 2, (kt + 2) % 3);
        const int buf = kt % 3;
        f16* Ah = pl[0] + buf * G0_P;
        f16* Wh = pl[1] + buf * G0_P;
#pragma unroll
        for (int ks = 0; ks < 2; ks++) {
            uint32_t bh[2][4];
#pragma unroll
            for (int p = 0; p < 2; p++) {
                int row = wn * 32 + p * 16 + ((lane >> 4) << 3) + (lane & 7);
                int kk = ks * 16 + ((lane >> 3) & 1) * 8;
                ldsm4(bh[p][0], bh[p][1], bh[p][2], bh[p][3], sptr(&Wh[row * 40 + kk]));
            }
#pragma unroll
            for (int mt = 0; mt < 4; mt++) {
                int row = wmi * 64 + mt * 16 + (lane & 15);
                int kk = ks * 16 + (lane >> 4) * 8;
                uint32_t ah[4];
                ldsm4(ah[0], ah[1], ah[2], ah[3], sptr(&Ah[row * 40 + kk]));
#pragma unroll
                for (int nt = 0; nt < 4; nt++) {
                    int p = nt >> 1, q = (nt & 1) * 2;
                    mma16816(acc[mt][nt], ah, bh[p][q], bh[p][q + 1]);
                }
            }
        }
    }
    __syncthreads();

#pragma unroll
    for (int mt = 0; mt < 4; mt++) {
#pragma unroll
        for (int nt = 0; nt < 4; nt++) {
            int col = cb + wn * 32 + nt * 8 + 2 * (lane & 3);
            int r0 = rb + wmi * 64 + mt * 16 + (lane >> 2);
            float b0 = bias[col], b1 = bias[col + 1];
            float v0 = (acc[mt][nt][0] + b0) * SCALE;
            float v1 = (acc[mt][nt][1] + b1) * SCALE;
            float v2 = (acc[mt][nt][2] + b0) * SCALE;
            float v3 = (acc[mt][nt][3] + b1) * SCALE;
            int h = col >> 5, d = col & 31;
            {
                int b = r0 >> 12, s = (r0 >> 3) & 511, vv = r0 & 7;
                int dst = (((h << 3) + vv) * 4 + b) * (SEG * DQ) + s * DQ + d;
                *(uint32_t*)&g_qh[dst] = pack_f16(v0, v1);
            }
            {
                int r1 = r0 + 8;
                int b = r1 >> 12, s = (r1 >> 3) & 511, vv = r1 & 7;
                int dst = (((h << 3) + vv) * 4 + b) * (SEG * DQ) + s * DQ + d;
                *(uint32_t*)&g_qh[dst] = pack_f16(v2, v3);
            }
        }
    }
}

// ---------------------------------------------------------------------------
// gemm1: fc + bias + residual + fused LN. Tile 64x256 (full row per CTA),
// 256 thr (8 warps 2x4, warp 32x64), BK=32, 3-stage cp.async, 2 CTAs/SM.
// ---------------------------------------------------------------------------
#define G1_A (64 * 40)
#define G1_W (256 * 40)
#define G1_STG ((G1_A + G1_W) * 2)            // 25600 B per stage
#define G1_SMEM (3 * G1_STG)                  // 76800

__global__ __launch_bounds__(256, 2) void gemm1(
    const f16* __restrict__ Ah_g, const f16* __restrict__ Wh_g,
    const float* __restrict__ bias, const float* __restrict__ resid,
    const float* __restrict__ gamma, const float* __restrict__ beta,
    float* __restrict__ Cp)
{
    extern __shared__ char smem_raw[];
    f16* Ahp = (f16*)smem_raw;          // [3][64][40]
    f16* Whp = Ahp + 3 * G1_A;          // [3][256][40]

    const int rb = blockIdx.x * 64;
    const int tid = threadIdx.x, lane = tid & 31, w = tid >> 5;
    const int wmi = w & 1, wn = w >> 1;   // 2 (row) x 4 (col)

    auto issue = [&](int kt, int buf) {
#pragma unroll
        for (int u = 0; u < 5; u++) {      // 1280 16B chunks: 256 A + 1024 W
            int idx = tid + u * 256;
            if (idx < 256) {
                int row = idx >> 2, q = (idx & 3) * 8;
                cpasync16(sptr(Ahp + buf * G1_A + row * 40 + q),
                          Ah_g + (size_t)(rb + row) * 256 + kt * 32 + q);
            } else {
                int i2 = idx - 256;
                int row = i2 >> 2, q = (i2 & 3) * 8;
                cpasync16(sptr(Whp + buf * G1_W + row * 40 + q),
                          Wh_g + (size_t)row * 256 + kt * 32 + q);
            }
        }
        asm volatile("cp.async.commit_group;");
    };

    float acc[2][8][4];
#pragma unroll
    for (int i = 0; i < 2; i++)
#pragma unroll
        for (int j = 0; j < 8; j++)
#pragma unroll
            for (int k = 0; k < 4; k++) acc[i][j][k] = 0.f;

    issue(0, 0);
    issue(1, 1);

#pragma unroll 1
    for (int kt = 0; kt < 8; kt++) {
        if (kt < 7) asm volatile("cp.async.wait_group 1;");
        else        asm volatile("cp.async.wait_group 0;");
        __syncthreads();
        if (kt < 6) issue(kt + 2, (kt + 2) % 3);
        const int buf = kt % 3;
        f16* Ah = Ahp + buf * G1_A;
        f16* Wh = Whp + buf * G1_W;
#pragma unroll
        for (int ks = 0; ks < 2; ks++) {
            uint32_t bh[4][4];
#pragma unroll
            for (int p = 0; p < 4; p++) {
                int row = wn * 64 + p * 16 + ((lane >> 4) << 3) + (lane & 7);
                int kk = ks * 16 + ((lane >> 3) & 1) * 8;
                ldsm4(bh[p][0], bh[p][1], bh[p][2], bh[p][3], sptr(&Wh[row * 40 + kk]));
            }
#pragma unroll
            for (int mt = 0; mt < 2; mt++) {
                int row = wmi * 32 + mt * 16 + (lane & 15);
                int kk = ks * 16 + (lane >> 4) * 8;
                uint32_t ah[4];
                ldsm4(ah[0], ah[1], ah[2], ah[3], sptr(&Ah[row * 40 + kk]));
#pragma unroll
                for (int nt = 0; nt < 8; nt++) {
                    int p = nt >> 1, q = (nt & 1) * 2;
                    mma16816(acc[mt][nt], ah, bh[p][q], bh[p][q + 1]);
                }
            }
        }
    }
    __syncthreads();

    // bias + residual + fused LayerNorm over full 256-wide rows
    float2* red = (float2*)smem_raw;                  // [64][4]
    float* mus = (float*)(smem_raw + 4096);           // [64]
    float* rss = (float*)(smem_raw + 4096 + 256);     // [64]

#pragma unroll
    for (int mt = 0; mt < 2; mt++) {
        float s0 = 0.f, q0 = 0.f, s1 = 0.f, q1 = 0.f;
        int rl = wmi * 32 + mt * 16 + (lane >> 2);
#pragma unroll
        for (int nt = 0; nt < 8; nt++) {
            int col = wn * 64 + nt * 8 + 2 * (lane & 3);
            float b0 = bias[col], b1 = bias[col + 1];
            float2 rx0 = *(const float2*)&resid[(size_t)(rb + rl) * 256 + col];
            float2 rx1 = *(const float2*)&resid[(size_t)(rb + rl + 8) * 256 + col];
            acc[mt][nt][0] += b0 + rx0.x;
            acc[mt][nt][1] += b1 + rx0.y;
            acc[mt][nt][2] += b0 + rx1.x;
            acc[mt][nt][3] += b1 + rx1.y;
            s0 += acc[mt][nt][0] + acc[mt][nt][1];
            q0 += acc[mt][nt][0] * acc[mt][nt][0] + acc[mt][nt][1] * acc[mt][nt][1];
            s1 += acc[mt][nt][2] + acc[mt][nt][3];
            q1 += acc[mt][nt][2] * acc[mt][nt][2] + acc[mt][nt][3] * acc[mt][nt][3];
        }
#pragma unroll
        for (int o = 1; o <= 2; o <<= 1) {
            s0 += __shfl_xor_sync(0xffffffffu, s0, o);
            q0 += __shfl_xor_sync(0xffffffffu, q0, o);
            s1 += __shfl_xor_sync(0xffffffffu, s1, o);
            q1 += __shfl_xor_sync(0xffffffffu, q1, o);
        }
        if ((lane & 3) == 0) {
            red[rl * 4 + wn] = make_float2(s0, q0);
            red[(rl + 8) * 4 + wn] = make_float2(s1, q1);
        }
    }
    __syncthreads();
    if (tid < 64) {
        float s = 0.f, q = 0.f;
#pragma unroll
        for (int j = 0; j < 4; j++) {
            float2 p = red[tid * 4 + j];
            s += p.x;
            q += p.y;
        }
        float mu = s * (1.f / 256.f);
        float var = q * (1.f / 256.f) - mu * mu;
        mus[tid] = mu;
        rss[tid] = rsqrtf(var + 1e-5f);
    }
    __syncthreads();
#pragma unroll
    for (int nt = 0; nt < 8; nt++) {
        int col = wn * 64 + nt * 8 + 2 * (lane & 3);
        float g0 = gamma[col], g1 = gamma[col + 1];
        float be0 = beta[col], be1 = beta[col + 1];
#pragma unroll
        for (int mt = 0; mt < 2; mt++) {
            int rl = wmi * 32 + mt * 16 + (lane >> 2);
            float mu0 = mus[rl], rs0 = rss[rl];
            float mu1 = mus[rl + 8], rs1 = rss[rl + 8];
            float2 o0 = { (acc[mt][nt][0] - mu0) * rs0 * g0 + be0,
                          (acc[mt][nt][1] - mu0) * rs0 * g1 + be1 };
            float2 o1 = { (acc[mt][nt][2] - mu1) * rs1 * g0 + be0,
                          (acc[mt][nt][3] - mu1) * rs1 * g1 + be1 };
            *(float2*)&Cp[(size_t)(rb + rl) * 256 + col] = o0;
            *(float2*)&Cp[(size_t)(rb + rl + 8) * 256 + col] = o1;
        }
    }
}

// ---------------------------------------------------------------------------
// Attention: 4 CTAs/group (128 query rows each), 128 thr (4 warps x 32 rows),
// up to 5 CTAs/SM. z fp16 in smem (40KB). Per chunk: preload z^T frags,
// ex2.f16x2 softmax, MMA1(ct+1), MMA2(ct) with preloaded frags.
// ---------------------------------------------------------------------------
struct AttnCtx {
    f16* zh;
    int lane;
    uint32_t qfh[2][2][4];
};

__device__ __forceinline__ void attn_mma1(AttnCtx& c, int ct, float s[2][2][4]) {
#pragma unroll
    for (int i = 0; i < 2; i++)
#pragma unroll
        for (int j = 0; j < 2; j++)
#pragma unroll
            for (int k = 0; k < 4; k++) s[i][j][k] = 0.f;
    const int t0 = ct * 16;
#pragma unroll
    for (int ks = 0; ks < 2; ks++) {
        int zr = t0 + ((c.lane >> 4) << 3) + (c.lane & 7);
        int zk = ks * 16 + ((c.lane >> 3) & 1) * 8;
        uint32_t zbh[4];
        ldsm4(zbh[0], zbh[1], zbh[2], zbh[3], sptr(&c.zh[zr * 40 + zk]));
#pragma unroll
        for (int mt = 0; mt < 2; mt++)
#pragma unroll
            for (int nt = 0; nt < 2; nt++)
                mma16816(s[mt][nt], c.qfh[mt][ks], zbh[nt * 2], zbh[nt * 2 + 1]);
    }
}

__device__ __forceinline__ void attn_softmax(float s[2][2][4], uint32_t pah[2][4],
                                             float dn[2][2]) {
#pragma unroll
    for (int mt = 0; mt < 2; mt++) {
#pragma unroll
        for (int nt = 0; nt < 2; nt++) {
            pah[mt][nt * 2]     = ex2_f16x2(pack_f16(s[mt][nt][0], s[mt][nt][1]));
            pah[mt][nt * 2 + 1] = ex2_f16x2(pack_f16(s[mt][nt][2], s[mt][nt][3]));
        }
        __half2 h0 = __hadd2(*(__half2*)&pah[mt][0], *(__half2*)&pah[mt][2]);
        __half2 h1 = __hadd2(*(__half2*)&pah[mt][1], *(__half2*)&pah[mt][3]);
        float2 f0 = __half22float2(h0);
        float2 f1 = __half22float2(h1);
        dn[mt][0] += f0.x + f0.y;
        dn[mt][1] += f1.x + f1.y;
    }
}

__global__ __launch_bounds__(128, 5) void attn_mma() {
    extern __shared__ __align__(16) f16 zsm[];
    AttnCtx c;
    c.zh = zsm;   // [512][40]

    const int g = blockIdx.x >> 2, quarter = blockIdx.x & 3;
    const int tid = threadIdx.x, w = tid >> 5;
    c.lane = tid & 31;
    const int lane = c.lane;
    const int h = g >> 5, v = (g >> 2) & 7, b = g & 3;

    const f16* zph = g_zh + (size_t)g * SEG * DQ;
#pragma unroll
    for (int u = 0; u < 16; u++) {
        int idx = tid + u * 128;
        int row = idx >> 2, qq = idx & 3;
        *(uint4*)&c.zh[row * 40 + qq * 8] = *(const uint4*)&zph[row * 32 + qq * 8];
    }

    const f16* qph = g_qh + (size_t)g * SEG * DQ;
    const int m0 = quarter * 128 + w * 32;
#pragma unroll
    for (int mt = 0; mt < 2; mt++)
#pragma unroll
        for (int ks = 0; ks < 2; ks++) {
            int row = m0 + mt * 16 + (lane >> 2);
            int kk = ks * 16 + 2 * (lane & 3);
            c.qfh[mt][ks][0] = *(const uint32_t*)&qph[row * 32 + kk];
            c.qfh[mt][ks][1] = *(const uint32_t*)&qph[(row + 8) * 32 + kk];
            c.qfh[mt][ks][2] = *(const uint32_t*)&qph[row * 32 + kk + 8];
            c.qfh[mt][ks][3] = *(const uint32_t*)&qph[(row + 8) * 32 + kk + 8];
        }

    float o[2][4][4];
#pragma unroll
    for (int i = 0; i < 2; i++)
#pragma unroll
        for (int j = 0; j < 4; j++)
#pragma unroll
            for (int k = 0; k < 4; k++) o[i][j][k] = 0.f;
    float dn[2][2] = {{0.f, 0.f}, {0.f, 0.f}};

    __syncthreads();

    float s[2][2][4];
    attn_mma1(c, 0, s);

#pragma unroll 1
    for (int ct = 0; ct < 32; ct++) {
        // preload z^T fragments for MMA2(ct) -- overlaps LDS latency w/ softmax
        uint32_t zth[2][4];
        const int t0 = ct * 16;
#pragma unroll
        for (int dp = 0; dp < 2; dp++) {
            int zr = t0 + (((lane >> 3) & 1) << 3) + (lane & 7);
            int zc = dp * 16 + (lane >> 4) * 8;
            ldsm4t(zth[dp][0], zth[dp][1], zth[dp][2], zth[dp][3],
                   sptr(&c.zh[zr * 40 + zc]));
        }
        uint32_t pah[2][4];
        attn_softmax(s, pah, dn);
        if (ct < 31) {
            float s2[2][2][4];
            attn_mma1(c, ct + 1, s2);
#pragma unroll
            for (int i = 0; i < 2; i++)
#pragma unroll
                for (int j = 0; j < 2; j++)
#pragma unroll
                    for (int k = 0; k < 4; k++) s[i][j][k] = s2[i][j][k];
        }
#pragma unroll
        for (int dp = 0; dp < 2; dp++)
#pragma unroll
            for (int mt = 0; mt < 2; mt++)
#pragma unroll
                for (int nt = 0; nt < 2; nt++)
                    mma16816(o[mt][dp * 2 + nt], pah[mt],
                             zth[dp][nt * 2], zth[dp][nt * 2 + 1]);
    }

    float inv[2][2];
#pragma unroll
    for (int mt = 0; mt < 2; mt++)
#pragma unroll
        for (int rh = 0; rh < 2; rh++) {
            float d = dn[mt][rh];
            d += __shfl_xor_sync(0xffffffffu, d, 1);
            d += __shfl_xor_sync(0xffffffffu, d, 2);
            inv[mt][rh] = __fdividef(1.f, d);
        }

    // store O plane, token-major
#pragma unroll
    for (int mt = 0; mt < 2; mt++) {
        int s0 = m0 + mt * 16 + (lane >> 2);
        int r0 = ((b * SEG + s0) * 8) + v;
        int r1 = ((b * SEG + s0 + 8) * 8) + v;
#pragma unroll
        for (int n = 0; n < 4; n++) {
            int col = h * 32 + n * 8 + 2 * (lane & 3);
            *(uint32_t*)&g_oh[(size_t)r0 * 256 + col] =
                pack_f16(o[mt][n][0] * inv[mt][0], o[mt][n][1] * inv[mt][0]);
            *(uint32_t*)&g_oh[(size_t)r1 * 256 + col] =
                pack_f16(o[mt][n][2] * inv[mt][1], o[mt][n][3] * inv[mt][1]);
        }
    }
}

// ---------------------------------------------------------------------------

extern "C" void kernel_launch(void* const* d_in, const int* in_sizes, int n_in,
                              void* d_out, int out_size)
{
    const float* x     = (const float*)d_in[0];
    const float* z     = (const float*)d_in[1];
    const float* wq    = (const float*)d_in[2];
    const float* wqb   = (const float*)d_in[3];
    const float* fcw   = (const float*)d_in[4];
    const float* fcb   = (const float*)d_in[5];
    const float* gamma = (const float*)d_in[6];
    const float* beta  = (const float*)d_in[7];
    float* y = (float*)d_out;

    static f16 *xh_p = nullptr, *oh_p, *wqh_p, *fh_p;
    if (!xh_p) {
        cudaGetSymbolAddress((void**)&xh_p, g_xh);
        cudaGetSymbolAddress((void**)&oh_p, g_oh);
        cudaGetSymbolAddress((void**)&wqh_p, g_wqh);
        cudaGetSymbolAddress((void**)&fh_p, g_fh);
        cudaFuncSetAttribute(gemm0, cudaFuncAttributeMaxDynamicSharedMemorySize, G0_SMEM);
        cudaFuncSetAttribute(gemm1, cudaFuncAttributeMaxDynamicSharedMemorySize, G1_SMEM);
        cudaFuncSetAttribute(attn_mma, cudaFuncAttributeMaxDynamicSharedMemorySize, 512 * 40 * 2);
    }

    prep<<<8320, 256>>>(z, x, wq, fcw);
    dim3 g0grid(2, 128);
    gemm0<<<g0grid, 256, G0_SMEM>>>(xh_p, wqh_p, wqb);
    attn_mma<<<NG * 4, 128, 512 * 40 * 2>>>();
    gemm1<<<256, 256, G1_SMEM>>>(oh_p, fh_p, fcb, x, gamma, beta, y);
}